// round 8
// baseline (speedup 1.0000x reference)
#include <cuda_runtime.h>
#include <cuda_fp16.h>
#include <cstdint>
#include <cstddef>

#define HID   256
#define NOBJ  64
#define BATCH 64
#define NCTA2 2048          // 64 b x 32 i-pairs

// ---------------- static device scratch ----------------
__device__ float g_U[BATCH * NOBJ * HID];    // xf @ W1[0:26]
__device__ float g_VQ[BATCH * NOBJ * HID];   // xf @ W1[26:52] + qst @ W1[52:180] + b1
__device__ uint4 g_Bh4[3 * 4 * 2048];        // 3 layers x 4 K-chunks x 32KB fragment-packed fp16 B
__device__ float g_partial[NCTA2 * HID];

// ---------------- helpers ----------------
__device__ __forceinline__ void cp16(uint32_t dst, const void* src) {
    asm volatile("cp.async.cg.shared.global [%0], [%1], 16;" :: "r"(dst), "l"(src) : "memory");
}
__device__ __forceinline__ void cp_commit() { asm volatile("cp.async.commit_group;" ::: "memory"); }
__device__ __forceinline__ void cp_wait0()  { asm volatile("cp.async.wait_group 0;" ::: "memory"); }

__device__ __forceinline__ void mma16816(float acc[4], uint32_t a0, uint32_t a1, uint32_t a2, uint32_t a3,
                                         uint32_t b0, uint32_t b1) {
    asm volatile("mma.sync.aligned.m16n8k16.row.col.f32.f16.f16.f32 "
                 "{%0,%1,%2,%3}, {%4,%5,%6,%7}, {%8,%9}, {%0,%1,%2,%3};"
                 : "+f"(acc[0]), "+f"(acc[1]), "+f"(acc[2]), "+f"(acc[3])
                 : "r"(a0), "r"(a1), "r"(a2), "r"(a3), "r"(b0), "r"(b1));
}
__device__ __forceinline__ uint32_t pack2(__half lo, __half hi) {
    return (uint32_t)__half_as_ushort(lo) | ((uint32_t)__half_as_ushort(hi) << 16);
}

// ---------------- k0: weight-pack (blocks 0..11) + first-layer projections (blocks 12..267) ----------------
__global__ __launch_bounds__(256) void k0(const float* __restrict__ x,
                                          const float* __restrict__ qst,
                                          const float* __restrict__ w1,
                                          const float* __restrict__ b1,
                                          const float* __restrict__ w2,
                                          const float* __restrict__ w3,
                                          const float* __restrict__ w4) {
    __shared__ __align__(16) unsigned char sraw[64 * 256 * 2];   // 32KB
    int bx = blockIdx.x, tid = threadIdx.x;

    if (bx < 12) {
        __half* sh = (__half*)sraw;
        int l = bx >> 2, kc = bx & 3;
        const float* src = (l == 0) ? w2 : (l == 1) ? w3 : w4;
#pragma unroll 8
        for (int p = 0; p < 64; p++) {
            int idx = tid + p * 256;
            sh[idx] = __float2half_rn(src[kc * 64 * 256 + idx]);
        }
        __syncthreads();
        uint4* dst = g_Bh4 + (l * 4 + kc) * 2048;
#pragma unroll
        for (int e0 = 0; e0 < 8; e0++) {
            int e = e0 * 256 + tid;
            int lane = e & 31, npair = (e >> 5) & 7, ks = (e >> 8) & 3, wn = e >> 10;
            int g = lane >> 2, t4 = lane & 3;
            int k0 = ks * 16 + 2 * t4;
            int n0 = wn * 128 + npair * 16 + g;
            uint4 v;
            v.x = pack2(sh[k0 * 256 + n0],       sh[(k0 + 1) * 256 + n0]);
            v.y = pack2(sh[(k0 + 8) * 256 + n0], sh[(k0 + 9) * 256 + n0]);
            v.z = pack2(sh[k0 * 256 + n0 + 8],       sh[(k0 + 1) * 256 + n0 + 8]);
            v.w = pack2(sh[(k0 + 8) * 256 + n0 + 8], sh[(k0 + 9) * 256 + n0 + 8]);
            dst[e] = v;
        }
    } else {
        float* xfs = (float*)sraw;            // [16][26]
        float* qs  = xfs + 16 * 26;           // [128]
        int bb = bx - 12;
        int b = bb >> 2, j0 = (bb & 3) * 16;
        int h = tid;

        for (int idx = tid; idx < 16 * 26; idx += 256) {
            int jl = idx / 26, c = idx % 26;
            int j = j0 + jl;
            float v;
            if (c < 24)       v = x[((size_t)b * 24 + c) * 64 + j];
            else if (c == 24) v = ((float)j * 0.125f - 4.0f) * 0.25f;
            else              v = ((float)(j & 7) - 4.0f) * 0.25f;
            xfs[jl * 26 + c] = v;
        }
        if (tid < 128) qs[tid] = qst[b * 128 + tid];
        __syncthreads();

        float wa[26], wb[26];
#pragma unroll
        for (int c = 0; c < 26; c++) {
            wa[c] = w1[c * HID + h];
            wb[c] = w1[(26 + c) * HID + h];
        }
        float q0 = b1[h], q1 = 0.f, q2 = 0.f, q3 = 0.f;
#pragma unroll 8
        for (int q = 0; q < 128; q += 4) {
            q0 += qs[q]     * w1[(52 + q)     * HID + h];
            q1 += qs[q + 1] * w1[(52 + q + 1) * HID + h];
            q2 += qs[q + 2] * w1[(52 + q + 2) * HID + h];
            q3 += qs[q + 3] * w1[(52 + q + 3) * HID + h];
        }
        float qp = (q0 + q1) + (q2 + q3);

        for (int jl = 0; jl < 16; jl++) {
            float u = 0.f, v = 0.f;
#pragma unroll
            for (int c = 0; c < 26; c++) {
                u += xfs[jl * 26 + c] * wa[c];
                v += xfs[jl * 26 + c] * wb[c];
            }
            g_U[((size_t)b * NOBJ + j0 + jl) * HID + h]  = u;
            g_VQ[((size_t)b * NOBJ + j0 + jl) * HID + h] = v + qp;
        }
    }
}

// ---------------- k2: fused g2->g3->g4 + pair-sum, 512 threads, f32-acc, pipelined ----------------
// CTA = (b, i-pair): M=128, N=256, K=256, 3 layers. Warp tile 32(M) x 64(N): wm=warp&3, wn=warp>>2.
// A smem: [kc(4)][ks4(4)][wm(4)][mt(2)][lane(32)] x 16B = 64KB.
// B smem: 2 x 64KB buffers (each = two 32KB fragment chunks = K=128 x N=256). 6 sync iterations.
#define B_OFF    65536u
#define WSUM_OFF 196608u
#define BIAS_OFF 200704u
#define K2_SMEM  203776u

__global__ __launch_bounds__(512, 1) void k2(const float* __restrict__ gb2,
                                             const float* __restrict__ gb3,
                                             const float* __restrict__ gb4) {
    extern __shared__ unsigned char sm[];
    unsigned char* Asm = sm;
    unsigned char* Bsm = sm + B_OFF;
    float* wsum  = (float*)(sm + WSUM_OFF);   // [16][64]
    float* biasS = (float*)(sm + BIAS_OFF);   // [3][256]
    const uint32_t sB = (uint32_t)__cvta_generic_to_shared(Bsm);

    const int tid = threadIdx.x, lane = tid & 31, warp = tid >> 5;
    const int wm = warp & 3, wn = warp >> 2;
    const int g = lane >> 2, t4 = lane & 3;
    const int b = blockIdx.x >> 5, i0 = (blockIdx.x & 31) * 2;

    if (tid < 256) { biasS[tid] = gb2[tid]; biasS[256 + tid] = gb3[tid]; biasS[512 + tid] = gb4[tid]; }

    // prefetch iteration 0 (chunks 0+1, 64KB) into buffer 0
    {
        const unsigned char* src = (const unsigned char*)g_Bh4;
#pragma unroll
        for (int t = 0; t < 8; t++) { int u = tid + t * 512; cp16(sB + u * 16, src + u * 16); }
        cp_commit();
    }

    // build layer-1 activations directly in fragment layout
    {
        const float* Ub = g_U  + (size_t)b * NOBJ * HID;
        const float* Vb = g_VQ + (size_t)b * NOBJ * HID;
        int kp = tid & 127, k0 = kp * 2;
        int kc = k0 >> 6, ks = (k0 >> 4) & 3, t4s = (k0 & 7) >> 1, pairsel = (k0 >> 3) & 1;
#pragma unroll 4
        for (int it = 0; it < 32; it++) {
            int row = it * 4 + (tid >> 7);
            float2 u = *(const float2*)(Ub + (row & 63) * HID + k0);
            float2 v = *(const float2*)(Vb + (i0 + (row >> 6)) * HID + k0);
            __half h0 = __float2half_rn(fmaxf(u.x + v.x, 0.f));
            __half h1 = __float2half_rn(fmaxf(u.y + v.y, 0.f));
            int wms = row >> 5, within = row & 31;
            int mts = (within >> 4) & 1, g8 = (within >> 3) & 1, gs = within & 7;
            int lanes = gs * 4 + t4s;
            uint32_t off = (uint32_t)(((((kc * 4 + ks) * 4 + wms) * 2 + mts) * 32 + lanes) * 16
                                      + pairsel * 8 + g8 * 4);
            *(uint32_t*)(Asm + off) = pack2(h0, h1);
        }
    }

    // per-warp constant parts of fragment addresses
    const uint32_t bfragoff = (uint32_t)(((((wn >> 1) * 4) * 8 + (wn & 1) * 4) * 32 + lane) * 16);

#pragma unroll 1
    for (int l = 0; l < 3; l++) {
        float acc[2][8][4];
#pragma unroll
        for (int mt = 0; mt < 2; mt++)
#pragma unroll
            for (int nt = 0; nt < 8; nt++) {
                acc[mt][nt][0] = 0.f; acc[mt][nt][1] = 0.f; acc[mt][nt][2] = 0.f; acc[mt][nt][3] = 0.f;
            }

#pragma unroll 1
        for (int it = 0; it < 2; it++) {
            const int i = l * 2 + it;            // global iteration 0..5
            cp_wait0();                          // 64KB for iteration i resident
            __syncthreads();                     // visible to all; buf (i+1)&1 reads (iter i-1) done
            if (i < 5) {
                const unsigned char* src = (const unsigned char*)g_Bh4 + (size_t)(i + 1) * 65536;
                uint32_t base = sB + (uint32_t)(((i + 1) & 1) * 65536);
#pragma unroll
                for (int t = 0; t < 8; t++) { int u = tid + t * 512; cp16(base + u * 16, src + u * 16); }
                cp_commit();
            }

            const unsigned char* Bb = Bsm + (i & 1) * 65536;

            // software-pipelined 8-step ks loop: load B frags for ks+1 while issuing mma for ks
            uint32_t bb[2][4][4];
            {
                const unsigned char* Bbase = Bb + bfragoff;   // ks=0: sub-chunk 0, ks4=0
#pragma unroll
                for (int np = 0; np < 4; np++) {
                    uint4 v = *(const uint4*)(Bbase + np * 512);
                    bb[0][np][0] = v.x; bb[0][np][1] = v.y; bb[0][np][2] = v.z; bb[0][np][3] = v.w;
                }
            }
#pragma unroll
            for (int ks = 0; ks < 8; ks++) {
                if (ks < 7) {
                    int ksn = ks + 1;
                    const unsigned char* Bbase = Bb + (ksn >> 2) * 32768
                        + (uint32_t)((ksn & 3) * (8 * 32 * 16)) + bfragoff;
#pragma unroll
                    for (int np = 0; np < 4; np++) {
                        uint4 v = *(const uint4*)(Bbase + np * 512);
                        bb[(ks + 1) & 1][np][0] = v.x; bb[(ks + 1) & 1][np][1] = v.y;
                        bb[(ks + 1) & 1][np][2] = v.z; bb[(ks + 1) & 1][np][3] = v.w;
                    }
                }
                const int kc = it * 2 + (ks >> 2), ks4 = ks & 3;
#pragma unroll
                for (int mt = 0; mt < 2; mt++) {
                    uint4 a = *(const uint4*)(Asm +
                        (size_t)((((((kc * 4 + ks4) * 4 + wm) * 2 + mt) * 32) + lane) * 16));
#pragma unroll
                    for (int nt = 0; nt < 8; nt++) {
                        int np = nt >> 1, s = (nt & 1) * 2;
                        mma16816(acc[mt][nt], a.x, a.y, a.z, a.w, bb[ks & 1][np][s], bb[ks & 1][np][s + 1]);
                    }
                }
            }
        }
        __syncthreads();   // all mma reads of A done before epilogue overwrites A

        if (l < 2) {
            const float* bias = biasS + l * 256;
#pragma unroll
            for (int mt = 0; mt < 2; mt++)
#pragma unroll
                for (int nt = 0; nt < 8; nt++) {
                    int c0 = wn * 64 + nt * 8 + 2 * t4;
                    float bz0 = bias[c0], bz1 = bias[c0 + 1];
                    __half2 hg  = __halves2half2(__float2half_rn(fmaxf(acc[mt][nt][0] + bz0, 0.f)),
                                                 __float2half_rn(fmaxf(acc[mt][nt][1] + bz1, 0.f)));
                    __half2 hg8 = __halves2half2(__float2half_rn(fmaxf(acc[mt][nt][2] + bz0, 0.f)),
                                                 __float2half_rn(fmaxf(acc[mt][nt][3] + bz1, 0.f)));
                    int kcn = c0 >> 6, ksn = (c0 >> 4) & 3, pairsel = (c0 >> 3) & 1;
                    uint32_t off = (uint32_t)(((((kcn * 4 + ksn) * 4 + wm) * 2 + mt) * 32 + lane) * 16 + pairsel * 8);
                    uint2 st; st.x = *(uint32_t*)&hg; st.y = *(uint32_t*)&hg8;
                    *(uint2*)(Asm + off) = st;
                }
            // next-layer mma reads ordered after these writes by the sync at top of next iteration
        } else {
            const float* bias = biasS + 512;
#pragma unroll
            for (int nt = 0; nt < 8; nt++) {
                int c0 = wn * 64 + nt * 8 + 2 * t4;
                float bz0 = bias[c0], bz1 = bias[c0 + 1];
                float s0 = fmaxf(acc[0][nt][0] + bz0, 0.f) + fmaxf(acc[0][nt][2] + bz0, 0.f)
                         + fmaxf(acc[1][nt][0] + bz0, 0.f) + fmaxf(acc[1][nt][2] + bz0, 0.f);
                float s1 = fmaxf(acc[0][nt][1] + bz1, 0.f) + fmaxf(acc[0][nt][3] + bz1, 0.f)
                         + fmaxf(acc[1][nt][1] + bz1, 0.f) + fmaxf(acc[1][nt][3] + bz1, 0.f);
                s0 += __shfl_xor_sync(0xffffffffu, s0, 4);
                s0 += __shfl_xor_sync(0xffffffffu, s0, 8);
                s0 += __shfl_xor_sync(0xffffffffu, s0, 16);
                s1 += __shfl_xor_sync(0xffffffffu, s1, 4);
                s1 += __shfl_xor_sync(0xffffffffu, s1, 8);
                s1 += __shfl_xor_sync(0xffffffffu, s1, 16);
                if (g == 0) {
                    wsum[warp * 64 + nt * 8 + 2 * t4]     = s0;
                    wsum[warp * 64 + nt * 8 + 2 * t4 + 1] = s1;
                }
            }
            __syncthreads();
            if (tid < 256) {
                int wnc = tid >> 6, cl = tid & 63;
                float s = wsum[(wnc * 4 + 0) * 64 + cl] + wsum[(wnc * 4 + 1) * 64 + cl]
                        + wsum[(wnc * 4 + 2) * 64 + cl] + wsum[(wnc * 4 + 3) * 64 + cl];
                g_partial[(size_t)blockIdx.x * HID + tid] = s;
            }
        }
    }
}

// ---------------- k3: tile reduction + f-MLP + log_softmax (1024 threads, k-split) ----------------
__global__ __launch_bounds__(1024) void k3(const float* __restrict__ f1w, const float* __restrict__ f1b,
                                           const float* __restrict__ f2w, const float* __restrict__ f2b,
                                           const float* __restrict__ f3w, const float* __restrict__ f3b,
                                           float* __restrict__ out) {
    __shared__ float part[4 * 256];
    __shared__ float xg[HID], y1[HID], y2[HID];
    int b = blockIdx.x, tid = threadIdx.x;
    int col = tid & 255, q = tid >> 8;   // q in 0..3

    {
        float s = 0.f;
#pragma unroll
        for (int t = 0; t < 8; t++)
            s += g_partial[((size_t)b * 32 + q * 8 + t) * HID + col];
        part[q * 256 + col] = s;
    }
    __syncthreads();
    if (q == 0) xg[col] = (part[col] + part[256 + col]) + (part[512 + col] + part[768 + col]);
    __syncthreads();

    {
        const float* W = f1w + q * 64 * HID;
        const float* xk = xg + q * 64;
        float a0 = 0.f, a1 = 0.f, a2 = 0.f, a3 = 0.f;
#pragma unroll 8
        for (int k = 0; k < 64; k += 4) {
            a0 += xk[k]     * W[k       * HID + col];
            a1 += xk[k + 1] * W[(k + 1) * HID + col];
            a2 += xk[k + 2] * W[(k + 2) * HID + col];
            a3 += xk[k + 3] * W[(k + 3) * HID + col];
        }
        part[q * 256 + col] = (a0 + a1) + (a2 + a3);
    }
    __syncthreads();
    if (q == 0) y1[col] = fmaxf((part[col] + part[256 + col]) + (part[512 + col] + part[768 + col]) + f1b[col], 0.f);
    __syncthreads();

    {
        const float* W = f2w + q * 64 * HID;
        const float* xk = y1 + q * 64;
        float a0 = 0.f, a1 = 0.f, a2 = 0.f, a3 = 0.f;
#pragma unroll 8
        for (int k = 0; k < 64; k += 4) {
            a0 += xk[k]     * W[k       * HID + col];
            a1 += xk[k + 1] * W[(k + 1) * HID + col];
            a2 += xk[k + 2] * W[(k + 2) * HID + col];
            a3 += xk[k + 3] * W[(k + 3) * HID + col];
        }
        part[q * 256 + col] = (a0 + a1) + (a2 + a3);
    }
    __syncthreads();
    if (q == 0) y2[col] = fmaxf((part[col] + part[256 + col]) + (part[512 + col] + part[768 + col]) + f2b[col], 0.f);
    __syncthreads();

    if (tid < 256) {
        int o = tid & 31, q8 = tid >> 5;
        if (o < 28) {
            const float* W = f3w + q8 * 32 * 28;
            const float* xk = y2 + q8 * 32;
            float a0 = 0.f, a1 = 0.f;
#pragma unroll
            for (int k = 0; k < 32; k += 2) {
                a0 += xk[k]     * W[k       * 28 + o];
                a1 += xk[k + 1] * W[(k + 1) * 28 + o];
            }
            part[q8 * 28 + o] = a0 + a1;
        }
    }
    __syncthreads();

    if (tid < 32) {
        float z;
        if (tid < 28) {
            z = f3b[tid];
#pragma unroll
            for (int p = 0; p < 8; p++) z += part[p * 28 + tid];
        } else {
            z = -1e30f;
        }
        float m = z;
#pragma unroll
        for (int o = 16; o > 0; o >>= 1) m = fmaxf(m, __shfl_xor_sync(0xffffffffu, m, o));
        float e = (tid < 28) ? expf(z - m) : 0.f;
        float se = e;
#pragma unroll
        for (int o = 16; o > 0; o >>= 1) se += __shfl_xor_sync(0xffffffffu, se, o);
        if (tid < 28) out[b * 28 + tid] = z - m - logf(se);
    }
}

// ---------------- launch ----------------
extern "C" void kernel_launch(void* const* d_in, const int* in_sizes, int n_in,
                              void* d_out, int out_size) {
    (void)in_sizes; (void)n_in; (void)out_size;
    const float* x   = (const float*)d_in[0];
    const float* qst = (const float*)d_in[1];
    const float* g1w = (const float*)d_in[2];
    const float* g1b = (const float*)d_in[3];
    const float* g2w = (const float*)d_in[4];
    const float* g2b = (const float*)d_in[5];
    const float* g3w = (const float*)d_in[6];
    const float* g3b = (const float*)d_in[7];
    const float* g4w = (const float*)d_in[8];
    const float* g4b = (const float*)d_in[9];
    const float* f1w = (const float*)d_in[10];
    const float* f1b = (const float*)d_in[11];
    const float* f2w = (const float*)d_in[12];
    const float* f2b = (const float*)d_in[13];
    const float* f3w = (const float*)d_in[14];
    const float* f3b = (const float*)d_in[15];
    float* out = (float*)d_out;

    cudaFuncSetAttribute((const void*)k2, cudaFuncAttributeMaxDynamicSharedMemorySize, (int)K2_SMEM);

    k0<<<268, 256>>>(x, qst, g1w, g1b, g2w, g3w, g4w);
    k2<<<NCTA2, 512, K2_SMEM>>>(g2b, g3b, g4b);
    k3<<<64, 1024>>>(f1w, f1b, f2w, f2b, f3w, f3b, out);
}

// round 9
// speedup vs baseline: 1.4658x; 1.4658x over previous
#include <cuda_runtime.h>
#include <cuda_fp16.h>
#include <cstdint>
#include <cstddef>

#define HID   256
#define NOBJ  64
#define BATCH 64
#define NCTA2 2048          // 64 b x 32 i-pairs

// ---------------- static device scratch ----------------
__device__ float g_U[BATCH * NOBJ * HID];    // xf @ W1[0:26]
__device__ float g_VQ[BATCH * NOBJ * HID];   // xf @ W1[26:52] + qst @ W1[52:180] + b1
__device__ uint4 g_Bh4[3 * 4 * 2048];        // 3 layers x 4 K-chunks x 32KB fragment-packed fp16 B
__device__ float g_partial[NCTA2 * HID];

// ---------------- helpers ----------------
__device__ __forceinline__ void cp16(uint32_t dst, const void* src) {
    asm volatile("cp.async.cg.shared.global [%0], [%1], 16;" :: "r"(dst), "l"(src) : "memory");
}
__device__ __forceinline__ void cp_commit() { asm volatile("cp.async.commit_group;" ::: "memory"); }
__device__ __forceinline__ void cp_wait0()  { asm volatile("cp.async.wait_group 0;" ::: "memory"); }

__device__ __forceinline__ void mma16816(float acc[4], uint32_t a0, uint32_t a1, uint32_t a2, uint32_t a3,
                                         uint32_t b0, uint32_t b1) {
    asm volatile("mma.sync.aligned.m16n8k16.row.col.f32.f16.f16.f32 "
                 "{%0,%1,%2,%3}, {%4,%5,%6,%7}, {%8,%9}, {%0,%1,%2,%3};"
                 : "+f"(acc[0]), "+f"(acc[1]), "+f"(acc[2]), "+f"(acc[3])
                 : "r"(a0), "r"(a1), "r"(a2), "r"(a3), "r"(b0), "r"(b1));
}
__device__ __forceinline__ uint32_t pack2(__half lo, __half hi) {
    return (uint32_t)__half_as_ushort(lo) | ((uint32_t)__half_as_ushort(hi) << 16);
}

// ---------------- k0: weight-pack (blocks 0..11) + first-layer projections (blocks 12..523) ----------------
__global__ __launch_bounds__(256) void k0(const float* __restrict__ x,
                                          const float* __restrict__ qst,
                                          const float* __restrict__ w1,
                                          const float* __restrict__ b1,
                                          const float* __restrict__ w2,
                                          const float* __restrict__ w3,
                                          const float* __restrict__ w4) {
    __shared__ __align__(16) unsigned char sraw[64 * 256 * 2];   // 32KB
    int bx = blockIdx.x, tid = threadIdx.x;

    if (bx < 12) {
        __half* sh = (__half*)sraw;
        int l = bx >> 2, kc = bx & 3;
        const float* src = (l == 0) ? w2 : (l == 1) ? w3 : w4;
#pragma unroll 8
        for (int p = 0; p < 64; p++) {
            int idx = tid + p * 256;
            sh[idx] = __float2half_rn(src[kc * 64 * 256 + idx]);
        }
        __syncthreads();
        uint4* dst = g_Bh4 + (l * 4 + kc) * 2048;
#pragma unroll
        for (int e0 = 0; e0 < 8; e0++) {
            int e = e0 * 256 + tid;
            int lane = e & 31, npair = (e >> 5) & 7, ks = (e >> 8) & 3, wn = e >> 10;
            int g = lane >> 2, t4 = lane & 3;
            int k0 = ks * 16 + 2 * t4;
            int n0 = wn * 128 + npair * 16 + g;
            uint4 v;
            v.x = pack2(sh[k0 * 256 + n0],       sh[(k0 + 1) * 256 + n0]);
            v.y = pack2(sh[(k0 + 8) * 256 + n0], sh[(k0 + 9) * 256 + n0]);
            v.z = pack2(sh[k0 * 256 + n0 + 8],       sh[(k0 + 1) * 256 + n0 + 8]);
            v.w = pack2(sh[(k0 + 8) * 256 + n0 + 8], sh[(k0 + 9) * 256 + n0 + 8]);
            dst[e] = v;
        }
    } else {
        // ---- first-layer projections: 8 CTAs per batch, 8 j-rows each ----
        float* xfs = (float*)sraw;            // [8][26]
        float* qs  = xfs + 8 * 26;            // [128]
        int bb = bx - 12;
        int b = bb >> 3, j0 = (bb & 7) * 8;
        int h = tid;

        for (int idx = tid; idx < 8 * 26; idx += 256) {
            int jl = idx / 26, c = idx % 26;
            int j = j0 + jl;
            float v;
            if (c < 24)       v = x[((size_t)b * 24 + c) * 64 + j];
            else if (c == 24) v = ((float)j * 0.125f - 4.0f) * 0.25f;
            else              v = ((float)(j & 7) - 4.0f) * 0.25f;
            xfs[jl * 26 + c] = v;
        }
        if (tid < 128) qs[tid] = qst[b * 128 + tid];
        __syncthreads();

        float wa[26], wb[26];
#pragma unroll
        for (int c = 0; c < 26; c++) {
            wa[c] = w1[c * HID + h];
            wb[c] = w1[(26 + c) * HID + h];
        }
        float q0 = b1[h], q1 = 0.f, q2 = 0.f, q3 = 0.f;
#pragma unroll 8
        for (int q = 0; q < 128; q += 4) {
            q0 += qs[q]     * w1[(52 + q)     * HID + h];
            q1 += qs[q + 1] * w1[(52 + q + 1) * HID + h];
            q2 += qs[q + 2] * w1[(52 + q + 2) * HID + h];
            q3 += qs[q + 3] * w1[(52 + q + 3) * HID + h];
        }
        float qp = (q0 + q1) + (q2 + q3);

#pragma unroll
        for (int jl = 0; jl < 8; jl++) {
            float u = 0.f, v = 0.f;
#pragma unroll
            for (int c = 0; c < 26; c++) {
                u += xfs[jl * 26 + c] * wa[c];
                v += xfs[jl * 26 + c] * wb[c];
            }
            g_U[((size_t)b * NOBJ + j0 + jl) * HID + h]  = u;
            g_VQ[((size_t)b * NOBJ + j0 + jl) * HID + h] = v + qp;
        }
    }
}

// ---------------- k2: fused g2->g3->g4 + pair-sum, 512 threads (R6 config) ----------------
// CTA = (b, i-pair): M=128, N=256, K=256, 3 layers. Warp tile 32(M) x 64(N): wm=warp&3, wn=warp>>2.
// A smem: [kc(4)][ks(4)][wm(4)][mt(2)][lane(32)] x 16B = 64KB. B: 2 x 32KB double-buffered.
#define B_OFF    65536u
#define WSUM_OFF 131072u
#define BIAS_OFF 135168u
#define K2_SMEM  138240u

__global__ __launch_bounds__(512, 1) void k2(const float* __restrict__ gb2,
                                             const float* __restrict__ gb3,
                                             const float* __restrict__ gb4) {
    extern __shared__ unsigned char sm[];
    unsigned char* Asm = sm;
    unsigned char* Bsm = sm + B_OFF;
    float* wsum  = (float*)(sm + WSUM_OFF);   // [16][64]
    float* biasS = (float*)(sm + BIAS_OFF);   // [3][256]
    const uint32_t sB = (uint32_t)__cvta_generic_to_shared(Bsm);

    const int tid = threadIdx.x, lane = tid & 31, warp = tid >> 5;
    const int wm = warp & 3, wn = warp >> 2;
    const int g = lane >> 2, t4 = lane & 3;
    const int b = blockIdx.x >> 5, i0 = (blockIdx.x & 31) * 2;

    if (tid < 256) { biasS[tid] = gb2[tid]; biasS[256 + tid] = gb3[tid]; biasS[512 + tid] = gb4[tid]; }

    // prefetch B chunk 0
    {
        const unsigned char* src = (const unsigned char*)g_Bh4;
#pragma unroll
        for (int t = 0; t < 4; t++) { int u = tid + t * 512; cp16(sB + u * 16, src + u * 16); }
        cp_commit();
    }

    // build layer-1 activations directly in fragment layout
    {
        const float* Ub = g_U  + (size_t)b * NOBJ * HID;
        const float* Vb = g_VQ + (size_t)b * NOBJ * HID;
        int kp = tid & 127, k0 = kp * 2;
        int kc = k0 >> 6, ks = (k0 >> 4) & 3, t4s = (k0 & 7) >> 1, pairsel = (k0 >> 3) & 1;
#pragma unroll 4
        for (int it = 0; it < 32; it++) {
            int row = it * 4 + (tid >> 7);
            float2 u = *(const float2*)(Ub + (row & 63) * HID + k0);
            float2 v = *(const float2*)(Vb + (i0 + (row >> 6)) * HID + k0);
            __half h0 = __float2half_rn(fmaxf(u.x + v.x, 0.f));
            __half h1 = __float2half_rn(fmaxf(u.y + v.y, 0.f));
            int wms = row >> 5, within = row & 31;
            int mts = (within >> 4) & 1, g8 = (within >> 3) & 1, gs = within & 7;
            int lanes = gs * 4 + t4s;
            uint32_t off = (uint32_t)(((((kc * 4 + ks) * 4 + wms) * 2 + mts) * 32 + lanes) * 16
                                      + pairsel * 8 + g8 * 4);
            *(uint32_t*)(Asm + off) = pack2(h0, h1);
        }
    }

#pragma unroll 1
    for (int l = 0; l < 3; l++) {
        float acc[2][8][4];
#pragma unroll
        for (int mt = 0; mt < 2; mt++)
#pragma unroll
            for (int nt = 0; nt < 8; nt++) {
                acc[mt][nt][0] = 0.f; acc[mt][nt][1] = 0.f; acc[mt][nt][2] = 0.f; acc[mt][nt][3] = 0.f;
            }

#pragma unroll 1
        for (int kc = 0; kc < 4; kc++) {
            const int c = l * 4 + kc;
            cp_wait0();          // chunk c resident
            __syncthreads();     // visible to all; reads of buf (c+1)&1 from iter c-1 done
            if (c < 11) {        // stream chunk c+1 into the other buffer
                const unsigned char* src = (const unsigned char*)g_Bh4 + (size_t)(c + 1) * 32768;
                uint32_t base = sB + (uint32_t)(((c + 1) & 1) * 32768);
#pragma unroll
                for (int t = 0; t < 4; t++) { int u = tid + t * 512; cp16(base + u * 16, src + u * 16); }
                cp_commit();
            }

            const unsigned char* Bb = Bsm + (c & 1) * 32768;
#pragma unroll
            for (int ks = 0; ks < 4; ks++) {
                uint32_t bb[4][4];
                {
                    const unsigned char* Bbase = Bb +
                        (size_t)(((((wn >> 1) * 4 + ks) * 8 + (wn & 1) * 4) * 32 + lane) * 16);
#pragma unroll
                    for (int np = 0; np < 4; np++) {
                        uint4 v = *(const uint4*)(Bbase + np * 512);
                        bb[np][0] = v.x; bb[np][1] = v.y; bb[np][2] = v.z; bb[np][3] = v.w;
                    }
                }
#pragma unroll
                for (int mt = 0; mt < 2; mt++) {
                    uint4 a = *(const uint4*)(Asm + (size_t)((((((kc * 4 + ks) * 4 + wm) * 2 + mt) * 32) + lane) * 16));
#pragma unroll
                    for (int nt = 0; nt < 8; nt++) {
                        int np = nt >> 1, s = (nt & 1) * 2;
                        mma16816(acc[mt][nt], a.x, a.y, a.z, a.w, bb[np][s], bb[np][s + 1]);
                    }
                }
            }
        }
        __syncthreads();   // all mma reads of A done before epilogue overwrites A

        if (l < 2) {
            const float* bias = biasS + l * 256;
#pragma unroll
            for (int mt = 0; mt < 2; mt++)
#pragma unroll
                for (int nt = 0; nt < 8; nt++) {
                    int c0 = wn * 64 + nt * 8 + 2 * t4;
                    float bz0 = bias[c0], bz1 = bias[c0 + 1];
                    __half2 hg  = __halves2half2(__float2half_rn(fmaxf(acc[mt][nt][0] + bz0, 0.f)),
                                                 __float2half_rn(fmaxf(acc[mt][nt][1] + bz1, 0.f)));
                    __half2 hg8 = __halves2half2(__float2half_rn(fmaxf(acc[mt][nt][2] + bz0, 0.f)),
                                                 __float2half_rn(fmaxf(acc[mt][nt][3] + bz1, 0.f)));
                    int kcn = c0 >> 6, ksn = (c0 >> 4) & 3, pairsel = (c0 >> 3) & 1;
                    uint32_t off = (uint32_t)(((((kcn * 4 + ksn) * 4 + wm) * 2 + mt) * 32 + lane) * 16 + pairsel * 8);
                    uint2 st; st.x = *(uint32_t*)&hg; st.y = *(uint32_t*)&hg8;
                    *(uint2*)(Asm + off) = st;
                }
            // next-layer mma reads ordered after these writes by the sync at top of kc=0
        } else {
            const float* bias = biasS + 512;
#pragma unroll
            for (int nt = 0; nt < 8; nt++) {
                int c0 = wn * 64 + nt * 8 + 2 * t4;
                float bz0 = bias[c0], bz1 = bias[c0 + 1];
                float s0 = fmaxf(acc[0][nt][0] + bz0, 0.f) + fmaxf(acc[0][nt][2] + bz0, 0.f)
                         + fmaxf(acc[1][nt][0] + bz0, 0.f) + fmaxf(acc[1][nt][2] + bz0, 0.f);
                float s1 = fmaxf(acc[0][nt][1] + bz1, 0.f) + fmaxf(acc[0][nt][3] + bz1, 0.f)
                         + fmaxf(acc[1][nt][1] + bz1, 0.f) + fmaxf(acc[1][nt][3] + bz1, 0.f);
                s0 += __shfl_xor_sync(0xffffffffu, s0, 4);
                s0 += __shfl_xor_sync(0xffffffffu, s0, 8);
                s0 += __shfl_xor_sync(0xffffffffu, s0, 16);
                s1 += __shfl_xor_sync(0xffffffffu, s1, 4);
                s1 += __shfl_xor_sync(0xffffffffu, s1, 8);
                s1 += __shfl_xor_sync(0xffffffffu, s1, 16);
                if (g == 0) {
                    wsum[warp * 64 + nt * 8 + 2 * t4]     = s0;
                    wsum[warp * 64 + nt * 8 + 2 * t4 + 1] = s1;
                }
            }
            __syncthreads();
            if (tid < 256) {
                int wnc = tid >> 6, cl = tid & 63;
                float s = wsum[(wnc * 4 + 0) * 64 + cl] + wsum[(wnc * 4 + 1) * 64 + cl]
                        + wsum[(wnc * 4 + 2) * 64 + cl] + wsum[(wnc * 4 + 3) * 64 + cl];
                g_partial[(size_t)blockIdx.x * HID + tid] = s;
            }
        }
    }
}

// ---------------- k3: tile reduction + f-MLP + log_softmax (1024 threads, k-split) ----------------
__global__ __launch_bounds__(1024) void k3(const float* __restrict__ f1w, const float* __restrict__ f1b,
                                           const float* __restrict__ f2w, const float* __restrict__ f2b,
                                           const float* __restrict__ f3w, const float* __restrict__ f3b,
                                           float* __restrict__ out) {
    __shared__ float part[4 * 256];
    __shared__ float xg[HID], y1[HID], y2[HID];
    int b = blockIdx.x, tid = threadIdx.x;
    int col = tid & 255, q = tid >> 8;   // q in 0..3

    {
        float s = 0.f;
#pragma unroll
        for (int t = 0; t < 8; t++)
            s += g_partial[((size_t)b * 32 + q * 8 + t) * HID + col];
        part[q * 256 + col] = s;
    }
    __syncthreads();
    if (q == 0) xg[col] = (part[col] + part[256 + col]) + (part[512 + col] + part[768 + col]);
    __syncthreads();

    {
        const float* W = f1w + q * 64 * HID;
        const float* xk = xg + q * 64;
        float a0 = 0.f, a1 = 0.f, a2 = 0.f, a3 = 0.f;
#pragma unroll 8
        for (int k = 0; k < 64; k += 4) {
            a0 += xk[k]     * W[k       * HID + col];
            a1 += xk[k + 1] * W[(k + 1) * HID + col];
            a2 += xk[k + 2] * W[(k + 2) * HID + col];
            a3 += xk[k + 3] * W[(k + 3) * HID + col];
        }
        part[q * 256 + col] = (a0 + a1) + (a2 + a3);
    }
    __syncthreads();
    if (q == 0) y1[col] = fmaxf((part[col] + part[256 + col]) + (part[512 + col] + part[768 + col]) + f1b[col], 0.f);
    __syncthreads();

    {
        const float* W = f2w + q * 64 * HID;
        const float* xk = y1 + q * 64;
        float a0 = 0.f, a1 = 0.f, a2 = 0.f, a3 = 0.f;
#pragma unroll 8
        for (int k = 0; k < 64; k += 4) {
            a0 += xk[k]     * W[k       * HID + col];
            a1 += xk[k + 1] * W[(k + 1) * HID + col];
            a2 += xk[k + 2] * W[(k + 2) * HID + col];
            a3 += xk[k + 3] * W[(k + 3) * HID + col];
        }
        part[q * 256 + col] = (a0 + a1) + (a2 + a3);
    }
    __syncthreads();
    if (q == 0) y2[col] = fmaxf((part[col] + part[256 + col]) + (part[512 + col] + part[768 + col]) + f2b[col], 0.f);
    __syncthreads();

    if (tid < 256) {
        int o = tid & 31, q8 = tid >> 5;
        if (o < 28) {
            const float* W = f3w + q8 * 32 * 28;
            const float* xk = y2 + q8 * 32;
            float a0 = 0.f, a1 = 0.f;
#pragma unroll
            for (int k = 0; k < 32; k += 2) {
                a0 += xk[k]     * W[k       * 28 + o];
                a1 += xk[k + 1] * W[(k + 1) * 28 + o];
            }
            part[q8 * 28 + o] = a0 + a1;
        }
    }
    __syncthreads();

    if (tid < 32) {
        float z;
        if (tid < 28) {
            z = f3b[tid];
#pragma unroll
            for (int p = 0; p < 8; p++) z += part[p * 28 + tid];
        } else {
            z = -1e30f;
        }
        float m = z;
#pragma unroll
        for (int o = 16; o > 0; o >>= 1) m = fmaxf(m, __shfl_xor_sync(0xffffffffu, m, o));
        float e = (tid < 28) ? expf(z - m) : 0.f;
        float se = e;
#pragma unroll
        for (int o = 16; o > 0; o >>= 1) se += __shfl_xor_sync(0xffffffffu, se, o);
        if (tid < 28) out[b * 28 + tid] = z - m - logf(se);
    }
}

// ---------------- launch ----------------
extern "C" void kernel_launch(void* const* d_in, const int* in_sizes, int n_in,
                              void* d_out, int out_size) {
    (void)in_sizes; (void)n_in; (void)out_size;
    const float* x   = (const float*)d_in[0];
    const float* qst = (const float*)d_in[1];
    const float* g1w = (const float*)d_in[2];
    const float* g1b = (const float*)d_in[3];
    const float* g2w = (const float*)d_in[4];
    const float* g2b = (const float*)d_in[5];
    const float* g3w = (const float*)d_in[6];
    const float* g3b = (const float*)d_in[7];
    const float* g4w = (const float*)d_in[8];
    const float* g4b = (const float*)d_in[9];
    const float* f1w = (const float*)d_in[10];
    const float* f1b = (const float*)d_in[11];
    const float* f2w = (const float*)d_in[12];
    const float* f2b = (const float*)d_in[13];
    const float* f3w = (const float*)d_in[14];
    const float* f3b = (const float*)d_in[15];
    float* out = (float*)d_out;

    cudaFuncSetAttribute((const void*)k2, cudaFuncAttributeMaxDynamicSharedMemorySize, (int)K2_SMEM);

    k0<<<524, 256>>>(x, qst, g1w, g1b, g2w, g3w, g4w);
    k2<<<NCTA2, 512, K2_SMEM>>>(g2b, g3b, g4b);
    k3<<<64, 1024>>>(f1w, f1b, f2w, f2b, f3w, f3b, out);
}

// round 11
// speedup vs baseline: 1.6241x; 1.1080x over previous
#include <cuda_runtime.h>
#include <cuda_fp16.h>
#include <cstdint>
#include <cstddef>

#define HID   256
#define NOBJ  64
#define BATCH 64
#define NCTA2 4096          // 64 b x 64 i

// ---------------- static device scratch ----------------
__device__ float g_U[BATCH * NOBJ * HID];    // xf @ W1[0:26]
__device__ float g_VQ[BATCH * NOBJ * HID];   // xf @ W1[26:52] + qst @ W1[52:180] + b1
__device__ uint4 g_Bh4[3 * 4 * 2048];        // 3 layers x 4 K-chunks x 32KB fragment-packed fp16 B
__device__ float g_partial[NCTA2 * HID];

// ---------------- helpers ----------------
__device__ __forceinline__ void cp16(uint32_t dst, const void* src) {
    asm volatile("cp.async.cg.shared.global [%0], [%1], 16;" :: "r"(dst), "l"(src) : "memory");
}
__device__ __forceinline__ void cp_commit() { asm volatile("cp.async.commit_group;" ::: "memory"); }
__device__ __forceinline__ void cp_wait0()  { asm volatile("cp.async.wait_group 0;" ::: "memory"); }

__device__ __forceinline__ void mma16816(float acc[4], uint32_t a0, uint32_t a1, uint32_t a2, uint32_t a3,
                                         uint32_t b0, uint32_t b1) {
    asm volatile("mma.sync.aligned.m16n8k16.row.col.f32.f16.f16.f32 "
                 "{%0,%1,%2,%3}, {%4,%5,%6,%7}, {%8,%9}, {%0,%1,%2,%3};"
                 : "+f"(acc[0]), "+f"(acc[1]), "+f"(acc[2]), "+f"(acc[3])
                 : "r"(a0), "r"(a1), "r"(a2), "r"(a3), "r"(b0), "r"(b1));
}
__device__ __forceinline__ uint32_t pack2(__half lo, __half hi) {
    return (uint32_t)__half_as_ushort(lo) | ((uint32_t)__half_as_ushort(hi) << 16);
}

// ---------------- k0: weight-pack (blocks 0..11) + first-layer projections (blocks 12..267) ----------------
__global__ __launch_bounds__(256) void k0(const float* __restrict__ x,
                                          const float* __restrict__ qst,
                                          const float* __restrict__ w1,
                                          const float* __restrict__ b1,
                                          const float* __restrict__ w2,
                                          const float* __restrict__ w3,
                                          const float* __restrict__ w4) {
    __shared__ __align__(16) unsigned char sraw[64 * 256 * 2];   // 32KB
    int bx = blockIdx.x, tid = threadIdx.x;

    if (bx < 12) {
        __half* sh = (__half*)sraw;
        int l = bx >> 2, kc = bx & 3;
        const float* src = (l == 0) ? w2 : (l == 1) ? w3 : w4;
#pragma unroll 8
        for (int p = 0; p < 64; p++) {
            int idx = tid + p * 256;
            sh[idx] = __float2half_rn(src[kc * 64 * 256 + idx]);
        }
        __syncthreads();
        uint4* dst = g_Bh4 + (l * 4 + kc) * 2048;
#pragma unroll
        for (int e0 = 0; e0 < 8; e0++) {
            int e = e0 * 256 + tid;
            int lane = e & 31, npair = (e >> 5) & 7, ks = (e >> 8) & 3, wn = e >> 10;
            int g = lane >> 2, t4 = lane & 3;
            int k0 = ks * 16 + 2 * t4;
            int n0 = wn * 128 + npair * 16 + g;
            uint4 v;
            v.x = pack2(sh[k0 * 256 + n0],       sh[(k0 + 1) * 256 + n0]);
            v.y = pack2(sh[(k0 + 8) * 256 + n0], sh[(k0 + 9) * 256 + n0]);
            v.z = pack2(sh[k0 * 256 + n0 + 8],       sh[(k0 + 1) * 256 + n0 + 8]);
            v.w = pack2(sh[(k0 + 8) * 256 + n0 + 8], sh[(k0 + 9) * 256 + n0 + 8]);
            dst[e] = v;
        }
    } else {
        // ---- first-layer projections: 4 CTAs per batch, 16 j-rows each ----
        float* xfs = (float*)sraw;            // [16][26]
        float* qs  = xfs + 16 * 26;           // [128]
        int bb = bx - 12;
        int b = bb >> 2, j0 = (bb & 3) * 16;
        int h = tid;

        for (int idx = tid; idx < 16 * 26; idx += 256) {
            int jl = idx / 26, c = idx % 26;
            int j = j0 + jl;
            float v;
            if (c < 24)       v = x[((size_t)b * 24 + c) * 64 + j];
            else if (c == 24) v = ((float)j * 0.125f - 4.0f) * 0.25f;
            else              v = ((float)(j & 7) - 4.0f) * 0.25f;
            xfs[jl * 26 + c] = v;
        }
        if (tid < 128) qs[tid] = qst[b * 128 + tid];
        __syncthreads();

        float wa[26], wb[26];
#pragma unroll
        for (int c = 0; c < 26; c++) {
            wa[c] = w1[c * HID + h];
            wb[c] = w1[(26 + c) * HID + h];
        }
        float q0 = b1[h], q1 = 0.f, q2 = 0.f, q3 = 0.f;
#pragma unroll 8
        for (int q = 0; q < 128; q += 4) {
            q0 += qs[q]     * w1[(52 + q)     * HID + h];
            q1 += qs[q + 1] * w1[(52 + q + 1) * HID + h];
            q2 += qs[q + 2] * w1[(52 + q + 2) * HID + h];
            q3 += qs[q + 3] * w1[(52 + q + 3) * HID + h];
        }
        float qp = (q0 + q1) + (q2 + q3);

        for (int jl = 0; jl < 16; jl++) {
            float u = 0.f, v = 0.f;
#pragma unroll
            for (int c = 0; c < 26; c++) {
                u += xfs[jl * 26 + c] * wa[c];
                v += xfs[jl * 26 + c] * wb[c];
            }
            g_U[((size_t)b * NOBJ + j0 + jl) * HID + h]  = u;
            g_VQ[((size_t)b * NOBJ + j0 + jl) * HID + h] = v + qp;
        }
    }
}

// ---------------- k2: fused g2->g3->g4 + pair-sum, M=64 tiles, 2 CTAs/SM ----------------
// CTA = (b, i): M=64 rows (j), N=256, K=256, 3 layers. 8 warps: wm=warp&1 (32-row m-tile), wn=warp>>1.
// A smem: [kc(4)][ks(4)][wm(2)][mt(2)][lane(32)] x 16B = 32KB. B: 2 x 32KB double-buffered.
#define B_OFF    32768u
#define WSUM_OFF 98304u
#define BIAS_OFF 100352u
#define K2_SMEM  103424u

__global__ __launch_bounds__(256, 2) void k2(const float* __restrict__ gb2,
                                             const float* __restrict__ gb3,
                                             const float* __restrict__ gb4) {
    extern __shared__ unsigned char sm[];
    unsigned char* Asm = sm;
    unsigned char* Bsm = sm + B_OFF;
    float* wsum  = (float*)(sm + WSUM_OFF);   // [8][64]
    float* biasS = (float*)(sm + BIAS_OFF);   // [3][256]
    const uint32_t sB = (uint32_t)__cvta_generic_to_shared(Bsm);

    const int tid = threadIdx.x, lane = tid & 31, warp = tid >> 5;
    const int wm = warp & 1, wn = warp >> 1;
    const int g = lane >> 2, t4 = lane & 3;
    const int b = blockIdx.x >> 6, i0 = blockIdx.x & 63;

    // 256 threads cover the full 256-wide bias vectors (fix of the R10 OOB)
    biasS[tid] = gb2[tid]; biasS[256 + tid] = gb3[tid]; biasS[512 + tid] = gb4[tid];

    // prefetch B chunk 0
    {
        const unsigned char* src = (const unsigned char*)g_Bh4;
#pragma unroll
        for (int t = 0; t < 8; t++) { int u = tid + t * 256; cp16(sB + u * 16, src + u * 16); }
        cp_commit();
    }

    // build layer-1 activations (64 rows) directly in fragment layout
    {
        const float* Ub = g_U  + (size_t)b * NOBJ * HID;
        const float* Vb = g_VQ + ((size_t)b * NOBJ + i0) * HID;
        int kp = tid & 127, k0 = kp * 2;
        int kc = k0 >> 6, ks = (k0 >> 4) & 3, t4s = (k0 & 7) >> 1, pairsel = (k0 >> 3) & 1;
        float2 v = *(const float2*)(Vb + k0);   // constant across rows for this CTA
#pragma unroll 4
        for (int it = 0; it < 32; it++) {
            int row = it * 2 + (tid >> 7);
            float2 u = *(const float2*)(Ub + row * HID + k0);
            __half h0 = __float2half_rn(fmaxf(u.x + v.x, 0.f));
            __half h1 = __float2half_rn(fmaxf(u.y + v.y, 0.f));
            int wms = row >> 5, within = row & 31;
            int mts = (within >> 4) & 1, g8 = (within >> 3) & 1, gs = within & 7;
            int lanes = gs * 4 + t4s;
            uint32_t off = (uint32_t)(((((kc * 4 + ks) * 2 + wms) * 2 + mts) * 32 + lanes) * 16
                                      + pairsel * 8 + g8 * 4);
            *(uint32_t*)(Asm + off) = pack2(h0, h1);
        }
    }

#pragma unroll 1
    for (int l = 0; l < 3; l++) {
        float acc[2][8][4];
#pragma unroll
        for (int mt = 0; mt < 2; mt++)
#pragma unroll
            for (int nt = 0; nt < 8; nt++) {
                acc[mt][nt][0] = 0.f; acc[mt][nt][1] = 0.f; acc[mt][nt][2] = 0.f; acc[mt][nt][3] = 0.f;
            }

#pragma unroll 1
        for (int kc = 0; kc < 4; kc++) {
            const int c = l * 4 + kc;
            cp_wait0();          // chunk c resident
            __syncthreads();     // visible to all; reads of buf (c+1)&1 from iter c-1 done
            if (c < 11) {        // stream chunk c+1 into the other buffer
                const unsigned char* src = (const unsigned char*)g_Bh4 + (size_t)(c + 1) * 32768;
                uint32_t base = sB + (uint32_t)(((c + 1) & 1) * 32768);
#pragma unroll
                for (int t = 0; t < 8; t++) { int u = tid + t * 256; cp16(base + u * 16, src + u * 16); }
                cp_commit();
            }

            const unsigned char* Bb = Bsm + (c & 1) * 32768;
#pragma unroll
            for (int ks = 0; ks < 4; ks++) {
                uint32_t bb[4][4];
                {
                    const unsigned char* Bbase = Bb +
                        (size_t)(((((wn >> 1) * 4 + ks) * 8 + (wn & 1) * 4) * 32 + lane) * 16);
#pragma unroll
                    for (int np = 0; np < 4; np++) {
                        uint4 v = *(const uint4*)(Bbase + np * 512);
                        bb[np][0] = v.x; bb[np][1] = v.y; bb[np][2] = v.z; bb[np][3] = v.w;
                    }
                }
#pragma unroll
                for (int mt = 0; mt < 2; mt++) {
                    uint4 a = *(const uint4*)(Asm + (size_t)((((((kc * 4 + ks) * 2 + wm) * 2 + mt) * 32) + lane) * 16));
#pragma unroll
                    for (int nt = 0; nt < 8; nt++) {
                        int np = nt >> 1, s = (nt & 1) * 2;
                        mma16816(acc[mt][nt], a.x, a.y, a.z, a.w, bb[np][s], bb[np][s + 1]);
                    }
                }
            }
        }
        __syncthreads();   // all mma reads of A done before epilogue overwrites A

        if (l < 2) {
            const float* bias = biasS + l * 256;
#pragma unroll
            for (int mt = 0; mt < 2; mt++)
#pragma unroll
                for (int nt = 0; nt < 8; nt++) {
                    int c0 = wn * 64 + nt * 8 + 2 * t4;
                    float bz0 = bias[c0], bz1 = bias[c0 + 1];
                    __half2 hg  = __halves2half2(__float2half_rn(fmaxf(acc[mt][nt][0] + bz0, 0.f)),
                                                 __float2half_rn(fmaxf(acc[mt][nt][1] + bz1, 0.f)));
                    __half2 hg8 = __halves2half2(__float2half_rn(fmaxf(acc[mt][nt][2] + bz0, 0.f)),
                                                 __float2half_rn(fmaxf(acc[mt][nt][3] + bz1, 0.f)));
                    int kcn = c0 >> 6, ksn = (c0 >> 4) & 3, pairsel = (c0 >> 3) & 1;
                    uint32_t off = (uint32_t)(((((kcn * 4 + ksn) * 2 + wm) * 2 + mt) * 32 + lane) * 16 + pairsel * 8);
                    uint2 st; st.x = *(uint32_t*)&hg; st.y = *(uint32_t*)&hg8;
                    *(uint2*)(Asm + off) = st;
                }
            // next-layer mma reads ordered after these writes by the sync at top of kc=0
        } else {
            const float* bias = biasS + 512;
#pragma unroll
            for (int nt = 0; nt < 8; nt++) {
                int c0 = wn * 64 + nt * 8 + 2 * t4;
                float bz0 = bias[c0], bz1 = bias[c0 + 1];
                float s0 = fmaxf(acc[0][nt][0] + bz0, 0.f) + fmaxf(acc[0][nt][2] + bz0, 0.f)
                         + fmaxf(acc[1][nt][0] + bz0, 0.f) + fmaxf(acc[1][nt][2] + bz0, 0.f);
                float s1 = fmaxf(acc[0][nt][1] + bz1, 0.f) + fmaxf(acc[0][nt][3] + bz1, 0.f)
                         + fmaxf(acc[1][nt][1] + bz1, 0.f) + fmaxf(acc[1][nt][3] + bz1, 0.f);
                s0 += __shfl_xor_sync(0xffffffffu, s0, 4);
                s0 += __shfl_xor_sync(0xffffffffu, s0, 8);
                s0 += __shfl_xor_sync(0xffffffffu, s0, 16);
                s1 += __shfl_xor_sync(0xffffffffu, s1, 4);
                s1 += __shfl_xor_sync(0xffffffffu, s1, 8);
                s1 += __shfl_xor_sync(0xffffffffu, s1, 16);
                if (g == 0) {
                    wsum[warp * 64 + nt * 8 + 2 * t4]     = s0;
                    wsum[warp * 64 + nt * 8 + 2 * t4 + 1] = s1;
                }
            }
            __syncthreads();
            {
                int wnc = tid >> 6, cl = tid & 63;   // warps for column group wnc: wnc*2, wnc*2+1
                float s = wsum[(wnc * 2 + 0) * 64 + cl] + wsum[(wnc * 2 + 1) * 64 + cl];
                g_partial[(size_t)blockIdx.x * HID + tid] = s;
            }
        }
    }
}

// ---------------- k3: tile reduction + f-MLP + log_softmax (1024 threads, k-split) ----------------
__global__ __launch_bounds__(1024) void k3(const float* __restrict__ f1w, const float* __restrict__ f1b,
                                           const float* __restrict__ f2w, const float* __restrict__ f2b,
                                           const float* __restrict__ f3w, const float* __restrict__ f3b,
                                           float* __restrict__ out) {
    __shared__ float part[4 * 256];
    __shared__ float xg[HID], y1[HID], y2[HID];
    int b = blockIdx.x, tid = threadIdx.x;
    int col = tid & 255, q = tid >> 8;   // q in 0..3

    {
        float s = 0.f;
#pragma unroll
        for (int t = 0; t < 16; t++)
            s += g_partial[((size_t)b * 64 + q * 16 + t) * HID + col];
        part[q * 256 + col] = s;
    }
    __syncthreads();
    if (q == 0) xg[col] = (part[col] + part[256 + col]) + (part[512 + col] + part[768 + col]);
    __syncthreads();

    {
        const float* W = f1w + q * 64 * HID;
        const float* xk = xg + q * 64;
        float a0 = 0.f, a1 = 0.f, a2 = 0.f, a3 = 0.f;
#pragma unroll 8
        for (int k = 0; k < 64; k += 4) {
            a0 += xk[k]     * W[k       * HID + col];
            a1 += xk[k + 1] * W[(k + 1) * HID + col];
            a2 += xk[k + 2] * W[(k + 2) * HID + col];
            a3 += xk[k + 3] * W[(k + 3) * HID + col];
        }
        part[q * 256 + col] = (a0 + a1) + (a2 + a3);
    }
    __syncthreads();
    if (q == 0) y1[col] = fmaxf((part[col] + part[256 + col]) + (part[512 + col] + part[768 + col]) + f1b[col], 0.f);
    __syncthreads();

    {
        const float* W = f2w + q * 64 * HID;
        const float* xk = y1 + q * 64;
        float a0 = 0.f, a1 = 0.f, a2 = 0.f, a3 = 0.f;
#pragma unroll 8
        for (int k = 0; k < 64; k += 4) {
            a0 += xk[k]     * W[k       * HID + col];
            a1 += xk[k + 1] * W[(k + 1) * HID + col];
            a2 += xk[k + 2] * W[(k + 2) * HID + col];
            a3 += xk[k + 3] * W[(k + 3) * HID + col];
        }
        part[q * 256 + col] = (a0 + a1) + (a2 + a3);
    }
    __syncthreads();
    if (q == 0) y2[col] = fmaxf((part[col] + part[256 + col]) + (part[512 + col] + part[768 + col]) + f2b[col], 0.f);
    __syncthreads();

    if (tid < 256) {
        int o = tid & 31, q8 = tid >> 5;
        if (o < 28) {
            const float* W = f3w + q8 * 32 * 28;
            const float* xk = y2 + q8 * 32;
            float a0 = 0.f, a1 = 0.f;
#pragma unroll
            for (int k = 0; k < 32; k += 2) {
                a0 += xk[k]     * W[k       * 28 + o];
                a1 += xk[k + 1] * W[(k + 1) * 28 + o];
            }
            part[q8 * 28 + o] = a0 + a1;
        }
    }
    __syncthreads();

    if (tid < 32) {
        float z;
        if (tid < 28) {
            z = f3b[tid];
#pragma unroll
            for (int p = 0; p < 8; p++) z += part[p * 28 + tid];
        } else {
            z = -1e30f;
        }
        float m = z;
#pragma unroll
        for (int o = 16; o > 0; o >>= 1) m = fmaxf(m, __shfl_xor_sync(0xffffffffu, m, o));
        float e = (tid < 28) ? expf(z - m) : 0.f;
        float se = e;
#pragma unroll
        for (int o = 16; o > 0; o >>= 1) se += __shfl_xor_sync(0xffffffffu, se, o);
        if (tid < 28) out[b * 28 + tid] = z - m - logf(se);
    }
}

// ---------------- launch ----------------
extern "C" void kernel_launch(void* const* d_in, const int* in_sizes, int n_in,
                              void* d_out, int out_size) {
    (void)in_sizes; (void)n_in; (void)out_size;
    const float* x   = (const float*)d_in[0];
    const float* qst = (const float*)d_in[1];
    const float* g1w = (const float*)d_in[2];
    const float* g1b = (const float*)d_in[3];
    const float* g2w = (const float*)d_in[4];
    const float* g2b = (const float*)d_in[5];
    const float* g3w = (const float*)d_in[6];
    const float* g3b = (const float*)d_in[7];
    const float* g4w = (const float*)d_in[8];
    const float* g4b = (const float*)d_in[9];
    const float* f1w = (const float*)d_in[10];
    const float* f1b = (const float*)d_in[11];
    const float* f2w = (const float*)d_in[12];
    const float* f2b = (const float*)d_in[13];
    const float* f3w = (const float*)d_in[14];
    const float* f3b = (const float*)d_in[15];
    float* out = (float*)d_out;

    cudaFuncSetAttribute((const void*)k2, cudaFuncAttributeMaxDynamicSharedMemorySize, (int)K2_SMEM);

    k0<<<268, 256>>>(x, qst, g1w, g1b, g2w, g3w, g4w);
    k2<<<NCTA2, 256, K2_SMEM>>>(g2b, g3b, g4b);
    k3<<<64, 1024>>>(f1w, f1b, f2w, f2b, f3w, f3b, out);
}

// round 12
// speedup vs baseline: 1.6789x; 1.0337x over previous
#include <cuda_runtime.h>
#include <cuda_fp16.h>
#include <cstdint>
#include <cstddef>

#define HID   256
#define NOBJ  64
#define BATCH 64
#define NCTA2 4096          // 64 b x 64 i

// ---------------- static device scratch ----------------
__device__ float g_U[BATCH * NOBJ * HID];    // xf @ W1[0:26]
__device__ float g_VQ[BATCH * NOBJ * HID];   // xf @ W1[26:52] + qst @ W1[52:180] + b1
__device__ uint4 g_Bh4[3 * 4 * 2048];        // 3 layers x 4 K-chunks x 32KB fragment-packed fp16 B
__device__ float g_partial[NCTA2 * HID];

// ---------------- helpers ----------------
__device__ __forceinline__ void cp16(uint32_t dst, const void* src) {
    asm volatile("cp.async.cg.shared.global [%0], [%1], 16;" :: "r"(dst), "l"(src) : "memory");
}
__device__ __forceinline__ void cp_commit() { asm volatile("cp.async.commit_group;" ::: "memory"); }
__device__ __forceinline__ void cp_wait0()  { asm volatile("cp.async.wait_group 0;" ::: "memory"); }

__device__ __forceinline__ void mma16816(float acc[4], uint32_t a0, uint32_t a1, uint32_t a2, uint32_t a3,
                                         uint32_t b0, uint32_t b1) {
    asm volatile("mma.sync.aligned.m16n8k16.row.col.f32.f16.f16.f32 "
                 "{%0,%1,%2,%3}, {%4,%5,%6,%7}, {%8,%9}, {%0,%1,%2,%3};"
                 : "+f"(acc[0]), "+f"(acc[1]), "+f"(acc[2]), "+f"(acc[3])
                 : "r"(a0), "r"(a1), "r"(a2), "r"(a3), "r"(b0), "r"(b1));
}
__device__ __forceinline__ uint32_t pack2(__half lo, __half hi) {
    return (uint32_t)__half_as_ushort(lo) | ((uint32_t)__half_as_ushort(hi) << 16);
}

// ---------------- k0: weight-pack (blocks 0..11) + first-layer projections (blocks 12..523) ----------------
// Projection split: CTA = (b, h-half, j-quarter): 128 h-cols x 16 j-rows.
// Thread = (h in half, jsub): handles one h column for 8 j rows. Per-thread chain 544 FFMA.
__global__ __launch_bounds__(256) void k0(const float* __restrict__ x,
                                          const float* __restrict__ qst,
                                          const float* __restrict__ w1,
                                          const float* __restrict__ b1,
                                          const float* __restrict__ w2,
                                          const float* __restrict__ w3,
                                          const float* __restrict__ w4) {
    __shared__ __align__(16) unsigned char sraw[64 * 256 * 2];   // 32KB
    int bx = blockIdx.x, tid = threadIdx.x;

    if (bx < 12) {
        __half* sh = (__half*)sraw;
        int l = bx >> 2, kc = bx & 3;
        const float* src = (l == 0) ? w2 : (l == 1) ? w3 : w4;
#pragma unroll 8
        for (int p = 0; p < 64; p++) {
            int idx = tid + p * 256;
            sh[idx] = __float2half_rn(src[kc * 64 * 256 + idx]);
        }
        __syncthreads();
        uint4* dst = g_Bh4 + (l * 4 + kc) * 2048;
#pragma unroll
        for (int e0 = 0; e0 < 8; e0++) {
            int e = e0 * 256 + tid;
            int lane = e & 31, npair = (e >> 5) & 7, ks = (e >> 8) & 3, wn = e >> 10;
            int g = lane >> 2, t4 = lane & 3;
            int k0 = ks * 16 + 2 * t4;
            int n0 = wn * 128 + npair * 16 + g;
            uint4 v;
            v.x = pack2(sh[k0 * 256 + n0],       sh[(k0 + 1) * 256 + n0]);
            v.y = pack2(sh[(k0 + 8) * 256 + n0], sh[(k0 + 9) * 256 + n0]);
            v.z = pack2(sh[k0 * 256 + n0 + 8],       sh[(k0 + 1) * 256 + n0 + 8]);
            v.w = pack2(sh[(k0 + 8) * 256 + n0 + 8], sh[(k0 + 9) * 256 + n0 + 8]);
            dst[e] = v;
        }
    } else {
        // ---- first-layer projections ----
        float* xfs = (float*)sraw;            // [16][26]
        float* qs  = xfs + 16 * 26;           // [128]
        int bb = bx - 12;                     // 0..511
        int b  = bb >> 3;                     // batch
        int hh = (bb >> 2) & 1;               // h half
        int jq = bb & 3;                      // j quarter
        int j0 = jq * 16;
        int h  = (tid & 127) + hh * 128;
        int jsub = tid >> 7;                  // 0/1: which 8 of the 16 j rows

        for (int idx = tid; idx < 16 * 26; idx += 256) {
            int jl = idx / 26, c = idx % 26;
            int j = j0 + jl;
            float v;
            if (c < 24)       v = x[((size_t)b * 24 + c) * 64 + j];
            else if (c == 24) v = ((float)j * 0.125f - 4.0f) * 0.25f;
            else              v = ((float)(j & 7) - 4.0f) * 0.25f;
            xfs[jl * 26 + c] = v;
        }
        if (tid < 128) qs[tid] = qst[b * 128 + tid];
        __syncthreads();

        float wa[26], wb[26];
#pragma unroll
        for (int c = 0; c < 26; c++) {
            wa[c] = w1[c * HID + h];
            wb[c] = w1[(26 + c) * HID + h];
        }
        float q0 = b1[h], q1 = 0.f, q2 = 0.f, q3 = 0.f;
#pragma unroll 8
        for (int q = 0; q < 128; q += 4) {
            q0 += qs[q]     * w1[(52 + q)     * HID + h];
            q1 += qs[q + 1] * w1[(52 + q + 1) * HID + h];
            q2 += qs[q + 2] * w1[(52 + q + 2) * HID + h];
            q3 += qs[q + 3] * w1[(52 + q + 3) * HID + h];
        }
        float qp = (q0 + q1) + (q2 + q3);

#pragma unroll
        for (int t = 0; t < 8; t++) {
            int jl = jsub * 8 + t;
            float u = 0.f, v = 0.f;
#pragma unroll
            for (int c = 0; c < 26; c++) {
                u += xfs[jl * 26 + c] * wa[c];
                v += xfs[jl * 26 + c] * wb[c];
            }
            g_U[((size_t)b * NOBJ + j0 + jl) * HID + h]  = u;
            g_VQ[((size_t)b * NOBJ + j0 + jl) * HID + h] = v + qp;
        }
    }
}

// ---------------- k2: fused g2->g3->g4 + pair-sum, M=64 tiles, 2 CTAs/SM ----------------
// CTA = (b, i): M=64 rows (j), N=256, K=256, 3 layers. 8 warps: wm=warp&1 (32-row m-tile), wn=warp>>1.
// A smem: [kc(4)][ks(4)][wm(2)][mt(2)][lane(32)] x 16B = 32KB. B: 2 x 32KB double-buffered.
#define B_OFF    32768u
#define WSUM_OFF 98304u
#define BIAS_OFF 100352u
#define K2_SMEM  103424u

__global__ __launch_bounds__(256, 2) void k2(const float* __restrict__ gb2,
                                             const float* __restrict__ gb3,
                                             const float* __restrict__ gb4) {
    extern __shared__ unsigned char sm[];
    unsigned char* Asm = sm;
    unsigned char* Bsm = sm + B_OFF;
    float* wsum  = (float*)(sm + WSUM_OFF);   // [8][64]
    float* biasS = (float*)(sm + BIAS_OFF);   // [3][256]
    const uint32_t sB = (uint32_t)__cvta_generic_to_shared(Bsm);

    const int tid = threadIdx.x, lane = tid & 31, warp = tid >> 5;
    const int wm = warp & 1, wn = warp >> 1;
    const int g = lane >> 2, t4 = lane & 3;
    const int b = blockIdx.x >> 6, i0 = blockIdx.x & 63;

    // prefetch B chunk 0 first (get the async stream going before any other work)
    {
        const unsigned char* src = (const unsigned char*)g_Bh4;
#pragma unroll
        for (int t = 0; t < 8; t++) { int u = tid + t * 256; cp16(sB + u * 16, src + u * 16); }
        cp_commit();
    }

    biasS[tid] = gb2[tid]; biasS[256 + tid] = gb3[tid]; biasS[512 + tid] = gb4[tid];

    // build layer-1 activations (64 rows) directly in fragment layout
    {
        const float* Ub = g_U  + (size_t)b * NOBJ * HID;
        const float* Vb = g_VQ + ((size_t)b * NOBJ + i0) * HID;
        int kp = tid & 127, k0 = kp * 2;
        int kc = k0 >> 6, ks = (k0 >> 4) & 3, t4s = (k0 & 7) >> 1, pairsel = (k0 >> 3) & 1;
        float2 v = *(const float2*)(Vb + k0);   // constant across rows for this CTA
#pragma unroll 8
        for (int it = 0; it < 32; it++) {
            int row = it * 2 + (tid >> 7);
            float2 u = *(const float2*)(Ub + row * HID + k0);
            __half h0 = __float2half_rn(fmaxf(u.x + v.x, 0.f));
            __half h1 = __float2half_rn(fmaxf(u.y + v.y, 0.f));
            int wms = row >> 5, within = row & 31;
            int mts = (within >> 4) & 1, g8 = (within >> 3) & 1, gs = within & 7;
            int lanes = gs * 4 + t4s;
            uint32_t off = (uint32_t)(((((kc * 4 + ks) * 2 + wms) * 2 + mts) * 32 + lanes) * 16
                                      + pairsel * 8 + g8 * 4);
            *(uint32_t*)(Asm + off) = pack2(h0, h1);
        }
    }

#pragma unroll 1
    for (int l = 0; l < 3; l++) {
        float acc[2][8][4];
#pragma unroll
        for (int mt = 0; mt < 2; mt++)
#pragma unroll
            for (int nt = 0; nt < 8; nt++) {
                acc[mt][nt][0] = 0.f; acc[mt][nt][1] = 0.f; acc[mt][nt][2] = 0.f; acc[mt][nt][3] = 0.f;
            }

#pragma unroll 1
        for (int kc = 0; kc < 4; kc++) {
            const int c = l * 4 + kc;
            cp_wait0();          // chunk c resident
            __syncthreads();     // visible to all; reads of buf (c+1)&1 from iter c-1 done
            if (c < 11) {        // stream chunk c+1 into the other buffer
                const unsigned char* src = (const unsigned char*)g_Bh4 + (size_t)(c + 1) * 32768;
                uint32_t base = sB + (uint32_t)(((c + 1) & 1) * 32768);
#pragma unroll
                for (int t = 0; t < 8; t++) { int u = tid + t * 256; cp16(base + u * 16, src + u * 16); }
                cp_commit();
            }

            const unsigned char* Bb = Bsm + (c & 1) * 32768;
#pragma unroll
            for (int ks = 0; ks < 4; ks++) {
                uint32_t bb[4][4];
                {
                    const unsigned char* Bbase = Bb +
                        (size_t)(((((wn >> 1) * 4 + ks) * 8 + (wn & 1) * 4) * 32 + lane) * 16);
#pragma unroll
                    for (int np = 0; np < 4; np++) {
                        uint4 v = *(const uint4*)(Bbase + np * 512);
                        bb[np][0] = v.x; bb[np][1] = v.y; bb[np][2] = v.z; bb[np][3] = v.w;
                    }
                }
#pragma unroll
                for (int mt = 0; mt < 2; mt++) {
                    uint4 a = *(const uint4*)(Asm + (size_t)((((((kc * 4 + ks) * 2 + wm) * 2 + mt) * 32) + lane) * 16));
#pragma unroll
                    for (int nt = 0; nt < 8; nt++) {
                        int np = nt >> 1, s = (nt & 1) * 2;
                        mma16816(acc[mt][nt], a.x, a.y, a.z, a.w, bb[np][s], bb[np][s + 1]);
                    }
                }
            }
        }
        __syncthreads();   // all mma reads of A done before epilogue overwrites A

        if (l < 2) {
            const float* bias = biasS + l * 256;
#pragma unroll
            for (int mt = 0; mt < 2; mt++)
#pragma unroll
                for (int nt = 0; nt < 8; nt++) {
                    int c0 = wn * 64 + nt * 8 + 2 * t4;
                    float bz0 = bias[c0], bz1 = bias[c0 + 1];
                    __half2 hg  = __halves2half2(__float2half_rn(fmaxf(acc[mt][nt][0] + bz0, 0.f)),
                                                 __float2half_rn(fmaxf(acc[mt][nt][1] + bz1, 0.f)));
                    __half2 hg8 = __halves2half2(__float2half_rn(fmaxf(acc[mt][nt][2] + bz0, 0.f)),
                                                 __float2half_rn(fmaxf(acc[mt][nt][3] + bz1, 0.f)));
                    int kcn = c0 >> 6, ksn = (c0 >> 4) & 3, pairsel = (c0 >> 3) & 1;
                    uint32_t off = (uint32_t)(((((kcn * 4 + ksn) * 2 + wm) * 2 + mt) * 32 + lane) * 16 + pairsel * 8);
                    uint2 st; st.x = *(uint32_t*)&hg; st.y = *(uint32_t*)&hg8;
                    *(uint2*)(Asm + off) = st;
                }
            // next-layer mma reads ordered after these writes by the sync at top of kc=0
        } else {
            const float* bias = biasS + 512;
#pragma unroll
            for (int nt = 0; nt < 8; nt++) {
                int c0 = wn * 64 + nt * 8 + 2 * t4;
                float bz0 = bias[c0], bz1 = bias[c0 + 1];
                float s0 = fmaxf(acc[0][nt][0] + bz0, 0.f) + fmaxf(acc[0][nt][2] + bz0, 0.f)
                         + fmaxf(acc[1][nt][0] + bz0, 0.f) + fmaxf(acc[1][nt][2] + bz0, 0.f);
                float s1 = fmaxf(acc[0][nt][1] + bz1, 0.f) + fmaxf(acc[0][nt][3] + bz1, 0.f)
                         + fmaxf(acc[1][nt][1] + bz1, 0.f) + fmaxf(acc[1][nt][3] + bz1, 0.f);
                s0 += __shfl_xor_sync(0xffffffffu, s0, 4);
                s0 += __shfl_xor_sync(0xffffffffu, s0, 8);
                s0 += __shfl_xor_sync(0xffffffffu, s0, 16);
                s1 += __shfl_xor_sync(0xffffffffu, s1, 4);
                s1 += __shfl_xor_sync(0xffffffffu, s1, 8);
                s1 += __shfl_xor_sync(0xffffffffu, s1, 16);
                if (g == 0) {
                    wsum[warp * 64 + nt * 8 + 2 * t4]     = s0;
                    wsum[warp * 64 + nt * 8 + 2 * t4 + 1] = s1;
                }
            }
            __syncthreads();
            {
                int wnc = tid >> 6, cl = tid & 63;   // warps for column group wnc: wnc*2, wnc*2+1
                float s = wsum[(wnc * 2 + 0) * 64 + cl] + wsum[(wnc * 2 + 1) * 64 + cl];
                g_partial[(size_t)blockIdx.x * HID + tid] = s;
            }
        }
    }
}

// ---------------- k3: tile reduction + f-MLP + log_softmax (1024 threads, k-split) ----------------
__global__ __launch_bounds__(1024) void k3(const float* __restrict__ f1w, const float* __restrict__ f1b,
                                           const float* __restrict__ f2w, const float* __restrict__ f2b,
                                           const float* __restrict__ f3w, const float* __restrict__ f3b,
                                           float* __restrict__ out) {
    __shared__ float part[4 * 256];
    __shared__ float xg[HID], y1[HID], y2[HID];
    int b = blockIdx.x, tid = threadIdx.x;
    int col = tid & 255, q = tid >> 8;   // q in 0..3

    {
        float s = 0.f;
#pragma unroll
        for (int t = 0; t < 16; t++)
            s += g_partial[((size_t)b * 64 + q * 16 + t) * HID + col];
        part[q * 256 + col] = s;
    }
    __syncthreads();
    if (q == 0) xg[col] = (part[col] + part[256 + col]) + (part[512 + col] + part[768 + col]);
    __syncthreads();

    {
        const float* W = f1w + q * 64 * HID;
        const float* xk = xg + q * 64;
        float a0 = 0.f, a1 = 0.f, a2 = 0.f, a3 = 0.f;
#pragma unroll 8
        for (int k = 0; k < 64; k += 4) {
            a0 += xk[k]     * W[k       * HID + col];
            a1 += xk[k + 1] * W[(k + 1) * HID + col];
            a2 += xk[k + 2] * W[(k + 2) * HID + col];
            a3 += xk[k + 3] * W[(k + 3) * HID + col];
        }
        part[q * 256 + col] = (a0 + a1) + (a2 + a3);
    }
    __syncthreads();
    if (q == 0) y1[col] = fmaxf((part[col] + part[256 + col]) + (part[512 + col] + part[768 + col]) + f1b[col], 0.f);
    __syncthreads();

    {
        const float* W = f2w + q * 64 * HID;
        const float* xk = y1 + q * 64;
        float a0 = 0.f, a1 = 0.f, a2 = 0.f, a3 = 0.f;
#pragma unroll 8
        for (int k = 0; k < 64; k += 4) {
            a0 += xk[k]     * W[k       * HID + col];
            a1 += xk[k + 1] * W[(k + 1) * HID + col];
            a2 += xk[k + 2] * W[(k + 2) * HID + col];
            a3 += xk[k + 3] * W[(k + 3) * HID + col];
        }
        part[q * 256 + col] = (a0 + a1) + (a2 + a3);
    }
    __syncthreads();
    if (q == 0) y2[col] = fmaxf((part[col] + part[256 + col]) + (part[512 + col] + part[768 + col]) + f2b[col], 0.f);
    __syncthreads();

    if (tid < 256) {
        int o = tid & 31, q8 = tid >> 5;
        if (o < 28) {
            const float* W = f3w + q8 * 32 * 28;
            const float* xk = y2 + q8 * 32;
            float a0 = 0.f, a1 = 0.f;
#pragma unroll
            for (int k = 0; k < 32; k += 2) {
                a0 += xk[k]     * W[k       * 28 + o];
                a1 += xk[k + 1] * W[(k + 1) * 28 + o];
            }
            part[q8 * 28 + o] = a0 + a1;
        }
    }
    __syncthreads();

    if (tid < 32) {
        float z;
        if (tid < 28) {
            z = f3b[tid];
#pragma unroll
            for (int p = 0; p < 8; p++) z += part[p * 28 + tid];
        } else {
            z = -1e30f;
        }
        float m = z;
#pragma unroll
        for (int o = 16; o > 0; o >>= 1) m = fmaxf(m, __shfl_xor_sync(0xffffffffu, m, o));
        float e = (tid < 28) ? expf(z - m) : 0.f;
        float se = e;
#pragma unroll
        for (int o = 16; o > 0; o >>= 1) se += __shfl_xor_sync(0xffffffffu, se, o);
        if (tid < 28) out[b * 28 + tid] = z - m - logf(se);
    }
}

// ---------------- launch ----------------
extern "C" void kernel_launch(void* const* d_in, const int* in_sizes, int n_in,
                              void* d_out, int out_size) {
    (void)in_sizes; (void)n_in; (void)out_size;
    const float* x   = (const float*)d_in[0];
    const float* qst = (const float*)d_in[1];
    const float* g1w = (const float*)d_in[2];
    const float* g1b = (const float*)d_in[3];
    const float* g2w = (const float*)d_in[4];
    const float* g2b = (const float*)d_in[5];
    const float* g3w = (const float*)d_in[6];
    const float* g3b = (const float*)d_in[7];
    const float* g4w = (const float*)d_in[8];
    const float* g4b = (const float*)d_in[9];
    const float* f1w = (const float*)d_in[10];
    const float* f1b = (const float*)d_in[11];
    const float* f2w = (const float*)d_in[12];
    const float* f2b = (const float*)d_in[13];
    const float* f3w = (const float*)d_in[14];
    const float* f3b = (const float*)d_in[15];
    float* out = (float*)d_out;

    cudaFuncSetAttribute((const void*)k2, cudaFuncAttributeMaxDynamicSharedMemorySize, (int)K2_SMEM);

    k0<<<524, 256>>>(x, qst, g1w, g1b, g2w, g3w, g4w);
    k2<<<NCTA2, 256, K2_SMEM>>>(g2b, g3b, g4b);
    k3<<<64, 1024>>>(f1w, f1b, f2w, f2b, f3w, f3b, out);
}

// round 13
// speedup vs baseline: 1.9445x; 1.1582x over previous
#include <cuda_runtime.h>
#include <cuda_fp16.h>
#include <cstdint>
#include <cstddef>

#define HID   256
#define NOBJ  64
#define BATCH 64
#define NCTA2 4096          // 64 b x 64 i

// ---------------- static device scratch ----------------
__device__ float g_U[BATCH * NOBJ * HID];    // xf @ W1[0:26]
__device__ float g_VQ[BATCH * NOBJ * HID];   // xf @ W1[26:52] + qst @ W1[52:180] + b1
__device__ uint4 g_Bh4[3 * 4 * 2048];        // 3 layers x 4 K-chunks x 32KB fragment-packed fp16 B
__device__ float g_partial[NCTA2 * HID];

// ---------------- helpers ----------------
__device__ __forceinline__ void mma16816(float acc[4], uint32_t a0, uint32_t a1, uint32_t a2, uint32_t a3,
                                         uint32_t b0, uint32_t b1) {
    asm volatile("mma.sync.aligned.m16n8k16.row.col.f32.f16.f16.f32 "
                 "{%0,%1,%2,%3}, {%4,%5,%6,%7}, {%8,%9}, {%0,%1,%2,%3};"
                 : "+f"(acc[0]), "+f"(acc[1]), "+f"(acc[2]), "+f"(acc[3])
                 : "r"(a0), "r"(a1), "r"(a2), "r"(a3), "r"(b0), "r"(b1));
}
__device__ __forceinline__ uint32_t pack2(__half lo, __half hi) {
    return (uint32_t)__half_as_ushort(lo) | ((uint32_t)__half_as_ushort(hi) << 16);
}

// ---------------- k0: weight-pack (blocks 0..11) + first-layer projections (blocks 12..523) ----------------
__global__ __launch_bounds__(256) void k0(const float* __restrict__ x,
                                          const float* __restrict__ qst,
                                          const float* __restrict__ w1,
                                          const float* __restrict__ b1,
                                          const float* __restrict__ w2,
                                          const float* __restrict__ w3,
                                          const float* __restrict__ w4) {
    __shared__ __align__(16) unsigned char sraw[64 * 256 * 2];   // 32KB
    int bx = blockIdx.x, tid = threadIdx.x;

    if (bx < 12) {
        __half* sh = (__half*)sraw;
        int l = bx >> 2, kc = bx & 3;
        const float* src = (l == 0) ? w2 : (l == 1) ? w3 : w4;
#pragma unroll 8
        for (int p = 0; p < 64; p++) {
            int idx = tid + p * 256;
            sh[idx] = __float2half_rn(src[kc * 64 * 256 + idx]);
        }
        __syncthreads();
        uint4* dst = g_Bh4 + (l * 4 + kc) * 2048;
#pragma unroll
        for (int e0 = 0; e0 < 8; e0++) {
            int e = e0 * 256 + tid;
            int lane = e & 31, npair = (e >> 5) & 7, ks = (e >> 8) & 3, wn = e >> 10;
            int g = lane >> 2, t4 = lane & 3;
            int k0 = ks * 16 + 2 * t4;
            int n0 = wn * 128 + npair * 16 + g;
            uint4 v;
            v.x = pack2(sh[k0 * 256 + n0],       sh[(k0 + 1) * 256 + n0]);
            v.y = pack2(sh[(k0 + 8) * 256 + n0], sh[(k0 + 9) * 256 + n0]);
            v.z = pack2(sh[k0 * 256 + n0 + 8],       sh[(k0 + 1) * 256 + n0 + 8]);
            v.w = pack2(sh[(k0 + 8) * 256 + n0 + 8], sh[(k0 + 9) * 256 + n0 + 8]);
            dst[e] = v;
        }
    } else {
        // ---- first-layer projections: CTA = (b, h-half, j-quarter) ----
        float* xfs = (float*)sraw;            // [16][26]
        float* qs  = xfs + 16 * 26;           // [128]
        int bb = bx - 12;                     // 0..511
        int b  = bb >> 3;
        int hh = (bb >> 2) & 1;
        int jq = bb & 3;
        int j0 = jq * 16;
        int h  = (tid & 127) + hh * 128;
        int jsub = tid >> 7;

        for (int idx = tid; idx < 16 * 26; idx += 256) {
            int jl = idx / 26, c = idx % 26;
            int j = j0 + jl;
            float v;
            if (c < 24)       v = x[((size_t)b * 24 + c) * 64 + j];
            else if (c == 24) v = ((float)j * 0.125f - 4.0f) * 0.25f;
            else              v = ((float)(j & 7) - 4.0f) * 0.25f;
            xfs[jl * 26 + c] = v;
        }
        if (tid < 128) qs[tid] = qst[b * 128 + tid];
        __syncthreads();

        float wa[26], wb[26];
#pragma unroll
        for (int c = 0; c < 26; c++) {
            wa[c] = w1[c * HID + h];
            wb[c] = w1[(26 + c) * HID + h];
        }
        float q0 = b1[h], q1 = 0.f, q2 = 0.f, q3 = 0.f;
#pragma unroll 8
        for (int q = 0; q < 128; q += 4) {
            q0 += qs[q]     * w1[(52 + q)     * HID + h];
            q1 += qs[q + 1] * w1[(52 + q + 1) * HID + h];
            q2 += qs[q + 2] * w1[(52 + q + 2) * HID + h];
            q3 += qs[q + 3] * w1[(52 + q + 3) * HID + h];
        }
        float qp = (q0 + q1) + (q2 + q3);

#pragma unroll
        for (int t = 0; t < 8; t++) {
            int jl = jsub * 8 + t;
            float u = 0.f, v = 0.f;
#pragma unroll
            for (int c = 0; c < 26; c++) {
                u += xfs[jl * 26 + c] * wa[c];
                v += xfs[jl * 26 + c] * wb[c];
            }
            g_U[((size_t)b * NOBJ + j0 + jl) * HID + h]  = u;
            g_VQ[((size_t)b * NOBJ + j0 + jl) * HID + h] = v + qp;
        }
    }
}

// ---------------- k2: fused g2->g3->g4 + pair-sum, M=64 tiles, 2 CTAs/SM, B via LDG ----------------
// CTA = (b, i): M=64 rows (j), N=256, K=256, 3 layers. 8 warps: wm=warp&1, wn=warp>>1 (64 cols).
// A smem only: [kc(4)][ks(4)][wm(2)][mt(2)][lane(32)] x 16B = 32KB. B fragments LDG'd from g_Bh4
// (L1-resident; co-resident CTA shares L1). Bias folded into acc init. 2 barriers per layer.
#define WSUM_OFF 32768u
#define BIAS_OFF 34816u
#define K2_SMEM  37888u

__global__ __launch_bounds__(256, 2) void k2(const float* __restrict__ gb2,
                                             const float* __restrict__ gb3,
                                             const float* __restrict__ gb4) {
    extern __shared__ unsigned char sm[];
    unsigned char* Asm = sm;
    float* wsum  = (float*)(sm + WSUM_OFF);   // [8][64]
    float* biasS = (float*)(sm + BIAS_OFF);   // [3][256]

    const int tid = threadIdx.x, lane = tid & 31, warp = tid >> 5;
    const int wm = warp & 1, wn = warp >> 1;
    const int g = lane >> 2, t4 = lane & 3;
    const int b = blockIdx.x >> 6, i0 = blockIdx.x & 63;

    biasS[tid] = gb2[tid]; biasS[256 + tid] = gb3[tid]; biasS[512 + tid] = gb4[tid];

    // build layer-1 activations (64 rows) directly in fragment layout
    {
        const float* Ub = g_U  + (size_t)b * NOBJ * HID;
        const float* Vb = g_VQ + ((size_t)b * NOBJ + i0) * HID;
        int kp = tid & 127, k0 = kp * 2;
        int kc = k0 >> 6, ks = (k0 >> 4) & 3, t4s = (k0 & 7) >> 1, pairsel = (k0 >> 3) & 1;
        float2 v = *(const float2*)(Vb + k0);   // constant across rows for this CTA
#pragma unroll 8
        for (int it = 0; it < 32; it++) {
            int row = it * 2 + (tid >> 7);
            float2 u = *(const float2*)(Ub + row * HID + k0);
            __half h0 = __float2half_rn(fmaxf(u.x + v.x, 0.f));
            __half h1 = __float2half_rn(fmaxf(u.y + v.y, 0.f));
            int wms = row >> 5, within = row & 31;
            int mts = (within >> 4) & 1, g8 = (within >> 3) & 1, gs = within & 7;
            int lanes = gs * 4 + t4s;
            uint32_t off = (uint32_t)(((((kc * 4 + ks) * 2 + wms) * 2 + mts) * 32 + lanes) * 16
                                      + pairsel * 8 + g8 * 4);
            *(uint32_t*)(Asm + off) = pack2(h0, h1);
        }
    }
    __syncthreads();   // A tile + biasS visible to all warps

    // per-warp constant part of the B fragment entry index within a (l,kc) block
    const int bent = (((wn >> 1) * 4) * 8 + (wn & 1) * 4) * 32 + lane;   // + ks*8*32 + np*32

#pragma unroll 1
    for (int l = 0; l < 3; l++) {
        // init accumulators with bias (epilogue then needs only relu)
        float acc[2][8][4];
#pragma unroll
        for (int nt = 0; nt < 8; nt++) {
            int c0 = wn * 64 + nt * 8 + 2 * t4;
            float bz0 = biasS[l * 256 + c0], bz1 = biasS[l * 256 + c0 + 1];
#pragma unroll
            for (int mt = 0; mt < 2; mt++) {
                acc[mt][nt][0] = bz0; acc[mt][nt][1] = bz1; acc[mt][nt][2] = bz0; acc[mt][nt][3] = bz1;
            }
        }

        const uint4* Bl = g_Bh4 + (size_t)l * 4 * 2048;
#pragma unroll
        for (int kc = 0; kc < 4; kc++) {
            const uint4* Bk = Bl + kc * 2048 + bent;
#pragma unroll
            for (int ks = 0; ks < 4; ks++) {
                uint4 bb[4];
#pragma unroll
                for (int np = 0; np < 4; np++)
                    bb[np] = __ldg(Bk + ks * 256 + np * 32);
#pragma unroll
                for (int mt = 0; mt < 2; mt++) {
                    uint4 a = *(const uint4*)(Asm +
                        (size_t)((((((kc * 4 + ks) * 2 + wm) * 2 + mt) * 32) + lane) * 16));
#pragma unroll
                    for (int nt = 0; nt < 8; nt++) {
                        int np = nt >> 1, s = (nt & 1) * 2;
                        uint32_t b0 = (s == 0) ? bb[np].x : bb[np].z;
                        uint32_t b1 = (s == 0) ? bb[np].y : bb[np].w;
                        mma16816(acc[mt][nt], a.x, a.y, a.z, a.w, b0, b1);
                    }
                }
            }
        }
        __syncthreads();   // all mma reads of A done before epilogue overwrites A

        if (l < 2) {
#pragma unroll
            for (int mt = 0; mt < 2; mt++)
#pragma unroll
                for (int nt = 0; nt < 8; nt++) {
                    int c0 = wn * 64 + nt * 8 + 2 * t4;
                    __half2 hg  = __halves2half2(__float2half_rn(fmaxf(acc[mt][nt][0], 0.f)),
                                                 __float2half_rn(fmaxf(acc[mt][nt][1], 0.f)));
                    __half2 hg8 = __halves2half2(__float2half_rn(fmaxf(acc[mt][nt][2], 0.f)),
                                                 __float2half_rn(fmaxf(acc[mt][nt][3], 0.f)));
                    int kcn = c0 >> 6, ksn = (c0 >> 4) & 3, pairsel = (c0 >> 3) & 1;
                    uint32_t off = (uint32_t)(((((kcn * 4 + ksn) * 2 + wm) * 2 + mt) * 32 + lane) * 16 + pairsel * 8);
                    uint2 st; st.x = *(uint32_t*)&hg; st.y = *(uint32_t*)&hg8;
                    *(uint2*)(Asm + off) = st;
                }
            __syncthreads();   // epilogue writes visible before next layer's A reads
        } else {
#pragma unroll
            for (int nt = 0; nt < 8; nt++) {
                int c0 = wn * 64 + nt * 8 + 2 * t4;
                float s0 = fmaxf(acc[0][nt][0], 0.f) + fmaxf(acc[0][nt][2], 0.f)
                         + fmaxf(acc[1][nt][0], 0.f) + fmaxf(acc[1][nt][2], 0.f);
                float s1 = fmaxf(acc[0][nt][1], 0.f) + fmaxf(acc[0][nt][3], 0.f)
                         + fmaxf(acc[1][nt][1], 0.f) + fmaxf(acc[1][nt][3], 0.f);
                s0 += __shfl_xor_sync(0xffffffffu, s0, 4);
                s0 += __shfl_xor_sync(0xffffffffu, s0, 8);
                s0 += __shfl_xor_sync(0xffffffffu, s0, 16);
                s1 += __shfl_xor_sync(0xffffffffu, s1, 4);
                s1 += __shfl_xor_sync(0xffffffffu, s1, 8);
                s1 += __shfl_xor_sync(0xffffffffu, s1, 16);
                if (g == 0) {
                    wsum[warp * 64 + nt * 8 + 2 * t4]     = s0;
                    wsum[warp * 64 + nt * 8 + 2 * t4 + 1] = s1;
                }
            }
            __syncthreads();
            {
                int wnc = tid >> 6, cl = tid & 63;
                float s = wsum[(wnc * 2 + 0) * 64 + cl] + wsum[(wnc * 2 + 1) * 64 + cl];
                g_partial[(size_t)blockIdx.x * HID + tid] = s;
            }
        }
    }
}

// ---------------- k3: tile reduction + f-MLP + log_softmax (1024 threads, k-split) ----------------
__global__ __launch_bounds__(1024) void k3(const float* __restrict__ f1w, const float* __restrict__ f1b,
                                           const float* __restrict__ f2w, const float* __restrict__ f2b,
                                           const float* __restrict__ f3w, const float* __restrict__ f3b,
                                           float* __restrict__ out) {
    __shared__ float part[4 * 256];
    __shared__ float xg[HID], y1[HID], y2[HID];
    int b = blockIdx.x, tid = threadIdx.x;
    int col = tid & 255, q = tid >> 8;

    {
        float s = 0.f;
#pragma unroll
        for (int t = 0; t < 16; t++)
            s += g_partial[((size_t)b * 64 + q * 16 + t) * HID + col];
        part[q * 256 + col] = s;
    }
    __syncthreads();
    if (q == 0) xg[col] = (part[col] + part[256 + col]) + (part[512 + col] + part[768 + col]);
    __syncthreads();

    {
        const float* W = f1w + q * 64 * HID;
        const float* xk = xg + q * 64;
        float a0 = 0.f, a1 = 0.f, a2 = 0.f, a3 = 0.f;
#pragma unroll 8
        for (int k = 0; k < 64; k += 4) {
            a0 += xk[k]     * W[k       * HID + col];
            a1 += xk[k + 1] * W[(k + 1) * HID + col];
            a2 += xk[k + 2] * W[(k + 2) * HID + col];
            a3 += xk[k + 3] * W[(k + 3) * HID + col];
        }
        part[q * 256 + col] = (a0 + a1) + (a2 + a3);
    }
    __syncthreads();
    if (q == 0) y1[col] = fmaxf((part[col] + part[256 + col]) + (part[512 + col] + part[768 + col]) + f1b[col], 0.f);
    __syncthreads();

    {
        const float* W = f2w + q * 64 * HID;
        const float* xk = y1 + q * 64;
        float a0 = 0.f, a1 = 0.f, a2 = 0.f, a3 = 0.f;
#pragma unroll 8
        for (int k = 0; k < 64; k += 4) {
            a0 += xk[k]     * W[k       * HID + col];
            a1 += xk[k + 1] * W[(k + 1) * HID + col];
            a2 += xk[k + 2] * W[(k + 2) * HID + col];
            a3 += xk[k + 3] * W[(k + 3) * HID + col];
        }
        part[q * 256 + col] = (a0 + a1) + (a2 + a3);
    }
    __syncthreads();
    if (q == 0) y2[col] = fmaxf((part[col] + part[256 + col]) + (part[512 + col] + part[768 + col]) + f2b[col], 0.f);
    __syncthreads();

    if (tid < 256) {
        int o = tid & 31, q8 = tid >> 5;
        if (o < 28) {
            const float* W = f3w + q8 * 32 * 28;
            const float* xk = y2 + q8 * 32;
            float a0 = 0.f, a1 = 0.f;
#pragma unroll
            for (int k = 0; k < 32; k += 2) {
                a0 += xk[k]     * W[k       * 28 + o];
                a1 += xk[k + 1] * W[(k + 1) * 28 + o];
            }
            part[q8 * 28 + o] = a0 + a1;
        }
    }
    __syncthreads();

    if (tid < 32) {
        float z;
        if (tid < 28) {
            z = f3b[tid];
#pragma unroll
            for (int p = 0; p < 8; p++) z += part[p * 28 + tid];
        } else {
            z = -1e30f;
        }
        float m = z;
#pragma unroll
        for (int o = 16; o > 0; o >>= 1) m = fmaxf(m, __shfl_xor_sync(0xffffffffu, m, o));
        float e = (tid < 28) ? expf(z - m) : 0.f;
        float se = e;
#pragma unroll
        for (int o = 16; o > 0; o >>= 1) se += __shfl_xor_sync(0xffffffffu, se, o);
        if (tid < 28) out[b * 28 + tid] = z - m - logf(se);
    }
}

// ---------------- launch ----------------
extern "C" void kernel_launch(void* const* d_in, const int* in_sizes, int n_in,
                              void* d_out, int out_size) {
    (void)in_sizes; (void)n_in; (void)out_size;
    const float* x   = (const float*)d_in[0];
    const float* qst = (const float*)d_in[1];
    const float* g1w = (const float*)d_in[2];
    const float* g1b = (const float*)d_in[3];
    const float* g2w = (const float*)d_in[4];
    const float* g2b = (const float*)d_in[5];
    const float* g3w = (const float*)d_in[6];
    const float* g3b = (const float*)d_in[7];
    const float* g4w = (const float*)d_in[8];
    const float* g4b = (const float*)d_in[9];
    const float* f1w = (const float*)d_in[10];
    const float* f1b = (const float*)d_in[11];
    const float* f2w = (const float*)d_in[12];
    const float* f2b = (const float*)d_in[13];
    const float* f3w = (const float*)d_in[14];
    const float* f3b = (const float*)d_in[15];
    float* out = (float*)d_out;

    cudaFuncSetAttribute((const void*)k2, cudaFuncAttributeMaxDynamicSharedMemorySize, (int)K2_SMEM);

    k0<<<524, 256>>>(x, qst, g1w, g1b, g2w, g3w, g4w);
    k2<<<NCTA2, 256, K2_SMEM>>>(g2b, g3b, g4b);
    k3<<<64, 1024>>>(f1w, f1b, f2w, f2b, f3w, f3b, out);
}

// round 14
// speedup vs baseline: 1.9573x; 1.0066x over previous
#include <cuda_runtime.h>
#include <cuda_fp16.h>
#include <cstdint>
#include <cstddef>

#define HID   256
#define NOBJ  64
#define BATCH 64
#define NCTA2 4096          // 64 b x 64 i

// ---------------- static device scratch ----------------
__device__ float g_U[BATCH * NOBJ * HID];    // xf @ W1[0:26]
__device__ float g_VQ[BATCH * NOBJ * HID];   // xf @ W1[26:52] + qst @ W1[52:180] + b1
__device__ uint4 g_Bh4[3 * 4 * 2048];        // 3 layers x 4 K-chunks x 32KB fragment-packed fp16 B
__device__ float g_partial[NCTA2 * HID];

// ---------------- helpers ----------------
__device__ __forceinline__ void mma16816(float acc[4], uint32_t a0, uint32_t a1, uint32_t a2, uint32_t a3,
                                         uint32_t b0, uint32_t b1) {
    asm volatile("mma.sync.aligned.m16n8k16.row.col.f32.f16.f16.f32 "
                 "{%0,%1,%2,%3}, {%4,%5,%6,%7}, {%8,%9}, {%0,%1,%2,%3};"
                 : "+f"(acc[0]), "+f"(acc[1]), "+f"(acc[2]), "+f"(acc[3])
                 : "r"(a0), "r"(a1), "r"(a2), "r"(a3), "r"(b0), "r"(b1));
}
__device__ __forceinline__ uint32_t pack2(__half lo, __half hi) {
    return (uint32_t)__half_as_ushort(lo) | ((uint32_t)__half_as_ushort(hi) << 16);
}

// ---------------- k0: weight-pack (blocks 0..11) + first-layer projections (blocks 12..523) ----------------
// Projection CTA = (b, h-half, j-quarter): 128 h-cols x 16 j-rows; thread = (h, role).
// role 0 computes U (wa only), role 1 computes VQ (wb + qst projection).
__global__ __launch_bounds__(256) void k0(const float* __restrict__ x,
                                          const float* __restrict__ qst,
                                          const float* __restrict__ w1,
                                          const float* __restrict__ b1,
                                          const float* __restrict__ w2,
                                          const float* __restrict__ w3,
                                          const float* __restrict__ w4) {
    __shared__ __align__(16) unsigned char sraw[64 * 256 * 2];   // 32KB
    int bx = blockIdx.x, tid = threadIdx.x;

    if (bx < 12) {
        __half* sh = (__half*)sraw;
        int l = bx >> 2, kc = bx & 3;
        const float* src = (l == 0) ? w2 : (l == 1) ? w3 : w4;
#pragma unroll 8
        for (int p = 0; p < 64; p++) {
            int idx = tid + p * 256;
            sh[idx] = __float2half_rn(src[kc * 64 * 256 + idx]);
        }
        __syncthreads();
        uint4* dst = g_Bh4 + (l * 4 + kc) * 2048;
#pragma unroll
        for (int e0 = 0; e0 < 8; e0++) {
            int e = e0 * 256 + tid;
            int lane = e & 31, npair = (e >> 5) & 7, ks = (e >> 8) & 3, wn = e >> 10;
            int g = lane >> 2, t4 = lane & 3;
            int k0 = ks * 16 + 2 * t4;
            int n0 = wn * 128 + npair * 16 + g;
            uint4 v;
            v.x = pack2(sh[k0 * 256 + n0],       sh[(k0 + 1) * 256 + n0]);
            v.y = pack2(sh[(k0 + 8) * 256 + n0], sh[(k0 + 9) * 256 + n0]);
            v.z = pack2(sh[k0 * 256 + n0 + 8],       sh[(k0 + 1) * 256 + n0 + 8]);
            v.w = pack2(sh[(k0 + 8) * 256 + n0 + 8], sh[(k0 + 9) * 256 + n0 + 8]);
            dst[e] = v;
        }
    } else {
        float* xfs = (float*)sraw;            // [16][26]
        float* qs  = xfs + 16 * 26;           // [128]
        int bb = bx - 12;                     // 0..511
        int b  = bb >> 3;
        int hh = (bb >> 2) & 1;
        int jq = bb & 3;
        int j0 = jq * 16;
        int h    = (tid & 127) + hh * 128;
        int role = tid >> 7;                  // 0: U, 1: VQ

        for (int idx = tid; idx < 16 * 26; idx += 256) {
            int jl = idx / 26, c = idx % 26;
            int j = j0 + jl;
            float v;
            if (c < 24)       v = x[((size_t)b * 24 + c) * 64 + j];
            else if (c == 24) v = ((float)j * 0.125f - 4.0f) * 0.25f;
            else              v = ((float)(j & 7) - 4.0f) * 0.25f;
            xfs[jl * 26 + c] = v;
        }
        if (tid < 128) qs[tid] = qst[b * 128 + tid];
        __syncthreads();

        if (role == 0) {
            float wa[26];
#pragma unroll
            for (int c = 0; c < 26; c++) wa[c] = w1[c * HID + h];
#pragma unroll
            for (int jl = 0; jl < 16; jl++) {
                float u = 0.f;
#pragma unroll
                for (int c = 0; c < 26; c++) u += xfs[jl * 26 + c] * wa[c];
                g_U[((size_t)b * NOBJ + j0 + jl) * HID + h] = u;
            }
        } else {
            float wb[26];
#pragma unroll
            for (int c = 0; c < 26; c++) wb[c] = w1[(26 + c) * HID + h];
            float q0 = b1[h], q1 = 0.f, q2 = 0.f, q3 = 0.f;
#pragma unroll 8
            for (int q = 0; q < 128; q += 4) {
                q0 += qs[q]     * w1[(52 + q)     * HID + h];
                q1 += qs[q + 1] * w1[(52 + q + 1) * HID + h];
                q2 += qs[q + 2] * w1[(52 + q + 2) * HID + h];
                q3 += qs[q + 3] * w1[(52 + q + 3) * HID + h];
            }
            float qp = (q0 + q1) + (q2 + q3);
#pragma unroll
            for (int jl = 0; jl < 16; jl++) {
                float v = 0.f;
#pragma unroll
                for (int c = 0; c < 26; c++) v += xfs[jl * 26 + c] * wb[c];
                g_VQ[((size_t)b * NOBJ + j0 + jl) * HID + h] = v + qp;
            }
        }
    }
}

// ---------------- k2: fused g2->g3->g4 + pair-sum, M=64 tiles, 2 CTAs/SM, B via LDG, A double-buffered ----------------
// CTA = (b, i): M=64, N=256, K=256, 3 layers. 8 warps: wm=warp&1, wn=warp>>1 (64 cols).
// A smem: 2 x 32KB buffers (layer l reads buf l&1, epilogue writes buf (l+1)&1 -> 1 barrier/layer).
// B fragments LDG'd from g_Bh4 (L1-resident; co-resident CTA shares L1). Bias folded into acc init.
#define A1_OFF   32768u
#define WSUM_OFF 65536u
#define BIAS_OFF 67584u
#define K2_SMEM  70656u

__global__ __launch_bounds__(256, 2) void k2(const float* __restrict__ gb2,
                                             const float* __restrict__ gb3,
                                             const float* __restrict__ gb4) {
    extern __shared__ unsigned char sm[];
    float* wsum  = (float*)(sm + WSUM_OFF);   // [8][64]
    float* biasS = (float*)(sm + BIAS_OFF);   // [3][256]

    const int tid = threadIdx.x, lane = tid & 31, warp = tid >> 5;
    const int wm = warp & 1, wn = warp >> 1;
    const int g = lane >> 2, t4 = lane & 3;
    const int b = blockIdx.x >> 6, i0 = blockIdx.x & 63;

    biasS[tid] = gb2[tid]; biasS[256 + tid] = gb3[tid]; biasS[512 + tid] = gb4[tid];

    // build layer-1 activations (64 rows) into buffer 0, fragment layout
    {
        unsigned char* A0 = sm;
        const float* Ub = g_U  + (size_t)b * NOBJ * HID;
        const float* Vb = g_VQ + ((size_t)b * NOBJ + i0) * HID;
        int kp = tid & 127, k0 = kp * 2;
        int kc = k0 >> 6, ks = (k0 >> 4) & 3, t4s = (k0 & 7) >> 1, pairsel = (k0 >> 3) & 1;
        float2 v = *(const float2*)(Vb + k0);   // constant across rows for this CTA
#pragma unroll 8
        for (int it = 0; it < 32; it++) {
            int row = it * 2 + (tid >> 7);
            float2 u = *(const float2*)(Ub + row * HID + k0);
            __half h0 = __float2half_rn(fmaxf(u.x + v.x, 0.f));
            __half h1 = __float2half_rn(fmaxf(u.y + v.y, 0.f));
            int wms = row >> 5, within = row & 31;
            int mts = (within >> 4) & 1, g8 = (within >> 3) & 1, gs = within & 7;
            int lanes = gs * 4 + t4s;
            uint32_t off = (uint32_t)(((((kc * 4 + ks) * 2 + wms) * 2 + mts) * 32 + lanes) * 16
                                      + pairsel * 8 + g8 * 4);
            *(uint32_t*)(A0 + off) = pack2(h0, h1);
        }
    }
    __syncthreads();   // A buffer 0 + biasS visible to all warps

    // per-warp constant part of the B fragment entry index within a (l,kc) block
    const int bent = (((wn >> 1) * 4) * 8 + (wn & 1) * 4) * 32 + lane;   // + ks*8*32 + np*32

#pragma unroll 1
    for (int l = 0; l < 3; l++) {
        unsigned char* Acur  = sm + (uint32_t)((l & 1) * 32768);
        unsigned char* Anext = sm + (uint32_t)(((l + 1) & 1) * 32768);

        // init accumulators with bias (epilogue then needs only relu)
        float acc[2][8][4];
#pragma unroll
        for (int nt = 0; nt < 8; nt++) {
            int c0 = wn * 64 + nt * 8 + 2 * t4;
            float bz0 = biasS[l * 256 + c0], bz1 = biasS[l * 256 + c0 + 1];
#pragma unroll
            for (int mt = 0; mt < 2; mt++) {
                acc[mt][nt][0] = bz0; acc[mt][nt][1] = bz1; acc[mt][nt][2] = bz0; acc[mt][nt][3] = bz1;
            }
        }

        const uint4* Bl = g_Bh4 + (size_t)l * 4 * 2048;
#pragma unroll
        for (int kc = 0; kc < 4; kc++) {
            const uint4* Bk = Bl + kc * 2048 + bent;
#pragma unroll
            for (int ks = 0; ks < 4; ks++) {
                uint4 bb[4];
#pragma unroll
                for (int np = 0; np < 4; np++)
                    bb[np] = __ldg(Bk + ks * 256 + np * 32);
#pragma unroll
                for (int mt = 0; mt < 2; mt++) {
                    uint4 a = *(const uint4*)(Acur +
                        (size_t)((((((kc * 4 + ks) * 2 + wm) * 2 + mt) * 32) + lane) * 16));
#pragma unroll
                    for (int nt = 0; nt < 8; nt++) {
                        int np = nt >> 1, s = (nt & 1) * 2;
                        uint32_t b0 = (s == 0) ? bb[np].x : bb[np].z;
                        uint32_t b1 = (s == 0) ? bb[np].y : bb[np].w;
                        mma16816(acc[mt][nt], a.x, a.y, a.z, a.w, b0, b1);
                    }
                }
            }
        }

        if (l < 2) {
            // epilogue writes the OTHER buffer -> no barrier needed before it
#pragma unroll
            for (int mt = 0; mt < 2; mt++)
#pragma unroll
                for (int nt = 0; nt < 8; nt++) {
                    int c0 = wn * 64 + nt * 8 + 2 * t4;
                    __half2 hg  = __halves2half2(__float2half_rn(fmaxf(acc[mt][nt][0], 0.f)),
                                                 __float2half_rn(fmaxf(acc[mt][nt][1], 0.f)));
                    __half2 hg8 = __halves2half2(__float2half_rn(fmaxf(acc[mt][nt][2], 0.f)),
                                                 __float2half_rn(fmaxf(acc[mt][nt][3], 0.f)));
                    int kcn = c0 >> 6, ksn = (c0 >> 4) & 3, pairsel = (c0 >> 3) & 1;
                    uint32_t off = (uint32_t)(((((kcn * 4 + ksn) * 2 + wm) * 2 + mt) * 32 + lane) * 16 + pairsel * 8);
                    uint2 st; st.x = *(uint32_t*)&hg; st.y = *(uint32_t*)&hg8;
                    *(uint2*)(Anext + off) = st;
                }
            __syncthreads();   // epilogue writes visible before next layer's A reads
        } else {
#pragma unroll
            for (int nt = 0; nt < 8; nt++) {
                int c0 = wn * 64 + nt * 8 + 2 * t4;
                float s0 = fmaxf(acc[0][nt][0], 0.f) + fmaxf(acc[0][nt][2], 0.f)
                         + fmaxf(acc[1][nt][0], 0.f) + fmaxf(acc[1][nt][2], 0.f);
                float s1 = fmaxf(acc[0][nt][1], 0.f) + fmaxf(acc[0][nt][3], 0.f)
                         + fmaxf(acc[1][nt][1], 0.f) + fmaxf(acc[1][nt][3], 0.f);
                s0 += __shfl_xor_sync(0xffffffffu, s0, 4);
                s0 += __shfl_xor_sync(0xffffffffu, s0, 8);
                s0 += __shfl_xor_sync(0xffffffffu, s0, 16);
                s1 += __shfl_xor_sync(0xffffffffu, s1, 4);
                s1 += __shfl_xor_sync(0xffffffffu, s1, 8);
                s1 += __shfl_xor_sync(0xffffffffu, s1, 16);
                if (g == 0) {
                    wsum[warp * 64 + nt * 8 + 2 * t4]     = s0;
                    wsum[warp * 64 + nt * 8 + 2 * t4 + 1] = s1;
                }
            }
            __syncthreads();
            {
                int wnc = tid >> 6, cl = tid & 63;
                float s = wsum[(wnc * 2 + 0) * 64 + cl] + wsum[(wnc * 2 + 1) * 64 + cl];
                g_partial[(size_t)blockIdx.x * HID + tid] = s;
            }
        }
    }
}

// ---------------- k3: tile reduction + f-MLP + log_softmax (1024 threads, k-split) ----------------
__global__ __launch_bounds__(1024) void k3(const float* __restrict__ f1w, const float* __restrict__ f1b,
                                           const float* __restrict__ f2w, const float* __restrict__ f2b,
                                           const float* __restrict__ f3w, const float* __restrict__ f3b,
                                           float* __restrict__ out) {
    __shared__ float part[4 * 256];
    __shared__ float xg[HID], y1[HID], y2[HID];
    int b = blockIdx.x, tid = threadIdx.x;
    int col = tid & 255, q = tid >> 8;

    {
        float s = 0.f;
#pragma unroll
        for (int t = 0; t < 16; t++)
            s += g_partial[((size_t)b * 64 + q * 16 + t) * HID + col];
        part[q * 256 + col] = s;
    }
    __syncthreads();
    if (q == 0) xg[col] = (part[col] + part[256 + col]) + (part[512 + col] + part[768 + col]);
    __syncthreads();

    {
        const float* W = f1w + q * 64 * HID;
        const float* xk = xg + q * 64;
        float a0 = 0.f, a1 = 0.f, a2 = 0.f, a3 = 0.f;
#pragma unroll 8
        for (int k = 0; k < 64; k += 4) {
            a0 += xk[k]     * W[k       * HID + col];
            a1 += xk[k + 1] * W[(k + 1) * HID + col];
            a2 += xk[k + 2] * W[(k + 2) * HID + col];
            a3 += xk[k + 3] * W[(k + 3) * HID + col];
        }
        part[q * 256 + col] = (a0 + a1) + (a2 + a3);
    }
    __syncthreads();
    if (q == 0) y1[col] = fmaxf((part[col] + part[256 + col]) + (part[512 + col] + part[768 + col]) + f1b[col], 0.f);
    __syncthreads();

    {
        const float* W = f2w + q * 64 * HID;
        const float* xk = y1 + q * 64;
        float a0 = 0.f, a1 = 0.f, a2 = 0.f, a3 = 0.f;
#pragma unroll 8
        for (int k = 0; k < 64; k += 4) {
            a0 += xk[k]     * W[k       * HID + col];
            a1 += xk[k + 1] * W[(k + 1) * HID + col];
            a2 += xk[k + 2] * W[(k + 2) * HID + col];
            a3 += xk[k + 3] * W[(k + 3) * HID + col];
        }
        part[q * 256 + col] = (a0 + a1) + (a2 + a3);
    }
    __syncthreads();
    if (q == 0) y2[col] = fmaxf((part[col] + part[256 + col]) + (part[512 + col] + part[768 + col]) + f2b[col], 0.f);
    __syncthreads();

    if (tid < 256) {
        int o = tid & 31, q8 = tid >> 5;
        if (o < 28) {
            const float* W = f3w + q8 * 32 * 28;
            const float* xk = y2 + q8 * 32;
            float a0 = 0.f, a1 = 0.f;
#pragma unroll
            for (int k = 0; k < 32; k += 2) {
                a0 += xk[k]     * W[k       * 28 + o];
                a1 += xk[k + 1] * W[(k + 1) * 28 + o];
            }
            part[q8 * 28 + o] = a0 + a1;
        }
    }
    __syncthreads();

    if (tid < 32) {
        float z;
        if (tid < 28) {
            z = f3b[tid];
#pragma unroll
            for (int p = 0; p < 8; p++) z += part[p * 28 + tid];
        } else {
            z = -1e30f;
        }
        float m = z;
#pragma unroll
        for (int o = 16; o > 0; o >>= 1) m = fmaxf(m, __shfl_xor_sync(0xffffffffu, m, o));
        float e = (tid < 28) ? expf(z - m) : 0.f;
        float se = e;
#pragma unroll
        for (int o = 16; o > 0; o >>= 1) se += __shfl_xor_sync(0xffffffffu, se, o);
        if (tid < 28) out[b * 28 + tid] = z - m - logf(se);
    }
}

// ---------------- launch ----------------
extern "C" void kernel_launch(void* const* d_in, const int* in_sizes, int n_in,
                              void* d_out, int out_size) {
    (void)in_sizes; (void)n_in; (void)out_size;
    const float* x   = (const float*)d_in[0];
    const float* qst = (const float*)d_in[1];
    const float* g1w = (const float*)d_in[2];
    const float* g1b = (const float*)d_in[3];
    const float* g2w = (const float*)d_in[4];
    const float* g2b = (const float*)d_in[5];
    const float* g3w = (const float*)d_in[6];
    const float* g3b = (const float*)d_in[7];
    const float* g4w = (const float*)d_in[8];
    const float* g4b = (const float*)d_in[9];
    const float* f1w = (const float*)d_in[10];
    const float* f1b = (const float*)d_in[11];
    const float* f2w = (const float*)d_in[12];
    const float* f2b = (const float*)d_in[13];
    const float* f3w = (const float*)d_in[14];
    const float* f3b = (const float*)d_in[15];
    float* out = (float*)d_out;

    cudaFuncSetAttribute((const void*)k2, cudaFuncAttributeMaxDynamicSharedMemorySize, (int)K2_SMEM);

    k0<<<524, 256>>>(x, qst, g1w, g1b, g2w, g3w, g4w);
    k2<<<NCTA2, 256, K2_SMEM>>>(g2b, g3b, g4b);
    k3<<<64, 1024>>>(f1w, f1b, f2w, f2b, f3w, f3b, out);
}

// round 15
// speedup vs baseline: 1.9966x; 1.0201x over previous
#include <cuda_runtime.h>
#include <cuda_fp16.h>
#include <cstdint>
#include <cstddef>

#define HID   256
#define NOBJ  64
#define BATCH 64
#define NCTA2 4096          // 64 b x 64 i

// ---------------- static device scratch ----------------
__device__ float g_U[BATCH * NOBJ * HID];    // xf @ W1[0:26]
__device__ float g_VQ[BATCH * NOBJ * HID];   // xf @ W1[26:52] + qst @ W1[52:180] + b1
__device__ uint4 g_Bh4[3 * 4 * 2048];        // 3 layers x 4 K-chunks x 32KB fragment-packed fp16 B
__device__ float g_partial[NCTA2 * HID];

// ---------------- helpers ----------------
__device__ __forceinline__ void mma16816(float acc[4], uint32_t a0, uint32_t a1, uint32_t a2, uint32_t a3,
                                         uint32_t b0, uint32_t b1) {
    asm volatile("mma.sync.aligned.m16n8k16.row.col.f32.f16.f16.f32 "
                 "{%0,%1,%2,%3}, {%4,%5,%6,%7}, {%8,%9}, {%0,%1,%2,%3};"
                 : "+f"(acc[0]), "+f"(acc[1]), "+f"(acc[2]), "+f"(acc[3])
                 : "r"(a0), "r"(a1), "r"(a2), "r"(a3), "r"(b0), "r"(b1));
}
__device__ __forceinline__ uint32_t pack2(__half lo, __half hi) {
    return (uint32_t)__half_as_ushort(lo) | ((uint32_t)__half_as_ushort(hi) << 16);
}

// ---------------- k0: weight-pack (blocks 0..11) + first-layer projections (blocks 12..523) ----------------
// Projection CTA = (b, h-half, j-quarter): 128 h-cols x 16 j-rows.
// Thread = (h in half, jsub): one h column for 8 j rows, computes both U and VQ (R12/R13 mapping).
__global__ __launch_bounds__(256) void k0(const float* __restrict__ x,
                                          const float* __restrict__ qst,
                                          const float* __restrict__ w1,
                                          const float* __restrict__ b1,
                                          const float* __restrict__ w2,
                                          const float* __restrict__ w3,
                                          const float* __restrict__ w4) {
    __shared__ __align__(16) unsigned char sraw[64 * 256 * 2];   // 32KB
    int bx = blockIdx.x, tid = threadIdx.x;

    if (bx < 12) {
        __half* sh = (__half*)sraw;
        int l = bx >> 2, kc = bx & 3;
        const float* src = (l == 0) ? w2 : (l == 1) ? w3 : w4;
#pragma unroll 8
        for (int p = 0; p < 64; p++) {
            int idx = tid + p * 256;
            sh[idx] = __float2half_rn(src[kc * 64 * 256 + idx]);
        }
        __syncthreads();
        uint4* dst = g_Bh4 + (l * 4 + kc) * 2048;
#pragma unroll
        for (int e0 = 0; e0 < 8; e0++) {
            int e = e0 * 256 + tid;
            int lane = e & 31, npair = (e >> 5) & 7, ks = (e >> 8) & 3, wn = e >> 10;
            int g = lane >> 2, t4 = lane & 3;
            int k0 = ks * 16 + 2 * t4;
            int n0 = wn * 128 + npair * 16 + g;
            uint4 v;
            v.x = pack2(sh[k0 * 256 + n0],       sh[(k0 + 1) * 256 + n0]);
            v.y = pack2(sh[(k0 + 8) * 256 + n0], sh[(k0 + 9) * 256 + n0]);
            v.z = pack2(sh[k0 * 256 + n0 + 8],       sh[(k0 + 1) * 256 + n0 + 8]);
            v.w = pack2(sh[(k0 + 8) * 256 + n0 + 8], sh[(k0 + 9) * 256 + n0 + 8]);
            dst[e] = v;
        }
    } else {
        float* xfs = (float*)sraw;            // [16][26]
        float* qs  = xfs + 16 * 26;           // [128]
        int bb = bx - 12;                     // 0..511
        int b  = bb >> 3;
        int hh = (bb >> 2) & 1;
        int jq = bb & 3;
        int j0 = jq * 16;
        int h  = (tid & 127) + hh * 128;
        int jsub = tid >> 7;                  // 0/1: which 8 of the 16 j rows

        for (int idx = tid; idx < 16 * 26; idx += 256) {
            int jl = idx / 26, c = idx % 26;
            int j = j0 + jl;
            float v;
            if (c < 24)       v = x[((size_t)b * 24 + c) * 64 + j];
            else if (c == 24) v = ((float)j * 0.125f - 4.0f) * 0.25f;
            else              v = ((float)(j & 7) - 4.0f) * 0.25f;
            xfs[jl * 26 + c] = v;
        }
        if (tid < 128) qs[tid] = qst[b * 128 + tid];
        __syncthreads();

        float wa[26], wb[26];
#pragma unroll
        for (int c = 0; c < 26; c++) {
            wa[c] = w1[c * HID + h];
            wb[c] = w1[(26 + c) * HID + h];
        }
        float q0 = b1[h], q1 = 0.f, q2 = 0.f, q3 = 0.f;
#pragma unroll 8
        for (int q = 0; q < 128; q += 4) {
            q0 += qs[q]     * w1[(52 + q)     * HID + h];
            q1 += qs[q + 1] * w1[(52 + q + 1) * HID + h];
            q2 += qs[q + 2] * w1[(52 + q + 2) * HID + h];
            q3 += qs[q + 3] * w1[(52 + q + 3) * HID + h];
        }
        float qp = (q0 + q1) + (q2 + q3);

#pragma unroll
        for (int t = 0; t < 8; t++) {
            int jl = jsub * 8 + t;
            float u = 0.f, v = 0.f;
#pragma unroll
            for (int c = 0; c < 26; c++) {
                u += xfs[jl * 26 + c] * wa[c];
                v += xfs[jl * 26 + c] * wb[c];
            }
            g_U[((size_t)b * NOBJ + j0 + jl) * HID + h]  = u;
            g_VQ[((size_t)b * NOBJ + j0 + jl) * HID + h] = v + qp;
        }
    }
}

// ---------------- k2: fused g2->g3->g4 + pair-sum, M=64 tiles, 2 CTAs/SM, B via LDG, A double-buffered ----------------
// CTA = (b, i): M=64, N=256, K=256, 3 layers. 8 warps: wm=warp&1, wn=warp>>1 (64 cols).
// A smem: 2 x 32KB buffers (layer l reads buf l&1, epilogue writes buf (l+1)&1 -> 1 barrier/layer).
// B fragments LDG'd from g_Bh4 (L1-resident; co-resident CTA shares L1). Bias folded into acc init.
#define A1_OFF   32768u
#define WSUM_OFF 65536u
#define BIAS_OFF 67584u
#define K2_SMEM  70656u

__global__ __launch_bounds__(256, 2) void k2(const float* __restrict__ gb2,
                                             const float* __restrict__ gb3,
                                             const float* __restrict__ gb4) {
    extern __shared__ unsigned char sm[];
    float* wsum  = (float*)(sm + WSUM_OFF);   // [8][64]
    float* biasS = (float*)(sm + BIAS_OFF);   // [3][256]

    const int tid = threadIdx.x, lane = tid & 31, warp = tid >> 5;
    const int wm = warp & 1, wn = warp >> 1;
    const int g = lane >> 2, t4 = lane & 3;
    const int b = blockIdx.x >> 6, i0 = blockIdx.x & 63;

    biasS[tid] = gb2[tid]; biasS[256 + tid] = gb3[tid]; biasS[512 + tid] = gb4[tid];

    // build layer-1 activations (64 rows) into buffer 0, fragment layout
    {
        unsigned char* A0 = sm;
        const float* Ub = g_U  + (size_t)b * NOBJ * HID;
        const float* Vb = g_VQ + ((size_t)b * NOBJ + i0) * HID;
        int kp = tid & 127, k0 = kp * 2;
        int kc = k0 >> 6, ks = (k0 >> 4) & 3, t4s = (k0 & 7) >> 1, pairsel = (k0 >> 3) & 1;
        float2 v = *(const float2*)(Vb + k0);   // constant across rows for this CTA
#pragma unroll 8
        for (int it = 0; it < 32; it++) {
            int row = it * 2 + (tid >> 7);
            float2 u = *(const float2*)(Ub + row * HID + k0);
            __half h0 = __float2half_rn(fmaxf(u.x + v.x, 0.f));
            __half h1 = __float2half_rn(fmaxf(u.y + v.y, 0.f));
            int wms = row >> 5, within = row & 31;
            int mts = (within >> 4) & 1, g8 = (within >> 3) & 1, gs = within & 7;
            int lanes = gs * 4 + t4s;
            uint32_t off = (uint32_t)(((((kc * 4 + ks) * 2 + wms) * 2 + mts) * 32 + lanes) * 16
                                      + pairsel * 8 + g8 * 4);
            *(uint32_t*)(A0 + off) = pack2(h0, h1);
        }
    }
    __syncthreads();   // A buffer 0 + biasS visible to all warps

    // per-warp constant part of the B fragment entry index within a (l,kc) block
    const int bent = (((wn >> 1) * 4) * 8 + (wn & 1) * 4) * 32 + lane;   // + ks*8*32 + np*32

#pragma unroll 1
    for (int l = 0; l < 3; l++) {
        unsigned char* Acur  = sm + (uint32_t)((l & 1) * 32768);
        unsigned char* Anext = sm + (uint32_t)(((l + 1) & 1) * 32768);

        // init accumulators with bias (epilogue then needs only relu)
        float acc[2][8][4];
#pragma unroll
        for (int nt = 0; nt < 8; nt++) {
            int c0 = wn * 64 + nt * 8 + 2 * t4;
            float bz0 = biasS[l * 256 + c0], bz1 = biasS[l * 256 + c0 + 1];
#pragma unroll
            for (int mt = 0; mt < 2; mt++) {
                acc[mt][nt][0] = bz0; acc[mt][nt][1] = bz1; acc[mt][nt][2] = bz0; acc[mt][nt][3] = bz1;
            }
        }

        const uint4* Bl = g_Bh4 + (size_t)l * 4 * 2048;
#pragma unroll
        for (int kc = 0; kc < 4; kc++) {
            const uint4* Bk = Bl + kc * 2048 + bent;
#pragma unroll
            for (int ks = 0; ks < 4; ks++) {
                uint4 bb[4];
#pragma unroll
                for (int np = 0; np < 4; np++)
                    bb[np] = __ldg(Bk + ks * 256 + np * 32);
#pragma unroll
                for (int mt = 0; mt < 2; mt++) {
                    uint4 a = *(const uint4*)(Acur +
                        (size_t)((((((kc * 4 + ks) * 2 + wm) * 2 + mt) * 32) + lane) * 16));
#pragma unroll
                    for (int nt = 0; nt < 8; nt++) {
                        int np = nt >> 1, s = (nt & 1) * 2;
                        uint32_t b0 = (s == 0) ? bb[np].x : bb[np].z;
                        uint32_t b1 = (s == 0) ? bb[np].y : bb[np].w;
                        mma16816(acc[mt][nt], a.x, a.y, a.z, a.w, b0, b1);
                    }
                }
            }
        }

        if (l < 2) {
            // epilogue writes the OTHER buffer -> no barrier needed before it
#pragma unroll
            for (int mt = 0; mt < 2; mt++)
#pragma unroll
                for (int nt = 0; nt < 8; nt++) {
                    int c0 = wn * 64 + nt * 8 + 2 * t4;
                    __half2 hg  = __halves2half2(__float2half_rn(fmaxf(acc[mt][nt][0], 0.f)),
                                                 __float2half_rn(fmaxf(acc[mt][nt][1], 0.f)));
                    __half2 hg8 = __halves2half2(__float2half_rn(fmaxf(acc[mt][nt][2], 0.f)),
                                                 __float2half_rn(fmaxf(acc[mt][nt][3], 0.f)));
                    int kcn = c0 >> 6, ksn = (c0 >> 4) & 3, pairsel = (c0 >> 3) & 1;
                    uint32_t off = (uint32_t)(((((kcn * 4 + ksn) * 2 + wm) * 2 + mt) * 32 + lane) * 16 + pairsel * 8);
                    uint2 st; st.x = *(uint32_t*)&hg; st.y = *(uint32_t*)&hg8;
                    *(uint2*)(Anext + off) = st;
                }
            __syncthreads();   // epilogue writes visible before next layer's A reads
        } else {
#pragma unroll
            for (int nt = 0; nt < 8; nt++) {
                int c0 = wn * 64 + nt * 8 + 2 * t4;
                float s0 = fmaxf(acc[0][nt][0], 0.f) + fmaxf(acc[0][nt][2], 0.f)
                         + fmaxf(acc[1][nt][0], 0.f) + fmaxf(acc[1][nt][2], 0.f);
                float s1 = fmaxf(acc[0][nt][1], 0.f) + fmaxf(acc[0][nt][3], 0.f)
                         + fmaxf(acc[1][nt][1], 0.f) + fmaxf(acc[1][nt][3], 0.f);
                s0 += __shfl_xor_sync(0xffffffffu, s0, 4);
                s0 += __shfl_xor_sync(0xffffffffu, s0, 8);
                s0 += __shfl_xor_sync(0xffffffffu, s0, 16);
                s1 += __shfl_xor_sync(0xffffffffu, s1, 4);
                s1 += __shfl_xor_sync(0xffffffffu, s1, 8);
                s1 += __shfl_xor_sync(0xffffffffu, s1, 16);
                if (g == 0) {
                    wsum[warp * 64 + nt * 8 + 2 * t4]     = s0;
                    wsum[warp * 64 + nt * 8 + 2 * t4 + 1] = s1;
                }
            }
            __syncthreads();
            {
                int wnc = tid >> 6, cl = tid & 63;
                float s = wsum[(wnc * 2 + 0) * 64 + cl] + wsum[(wnc * 2 + 1) * 64 + cl];
                g_partial[(size_t)blockIdx.x * HID + tid] = s;
            }
        }
    }
}

// ---------------- k3: tile reduction + f-MLP + log_softmax (1024 threads, k-split) ----------------
__global__ __launch_bounds__(1024) void k3(const float* __restrict__ f1w, const float* __restrict__ f1b,
                                           const float* __restrict__ f2w, const float* __restrict__ f2b,
                                           const float* __restrict__ f3w, const float* __restrict__ f3b,
                                           float* __restrict__ out) {
    __shared__ float part[4 * 256];
    __shared__ float xg[HID], y1[HID], y2[HID];
    int b = blockIdx.x, tid = threadIdx.x;
    int col = tid & 255, q = tid >> 8;

    {
        float s = 0.f;
#pragma unroll
        for (int t = 0; t < 16; t++)
            s += g_partial[((size_t)b * 64 + q * 16 + t) * HID + col];
        part[q * 256 + col] = s;
    }
    __syncthreads();
    if (q == 0) xg[col] = (part[col] + part[256 + col]) + (part[512 + col] + part[768 + col]);
    __syncthreads();

    {
        const float* W = f1w + q * 64 * HID;
        const float* xk = xg + q * 64;
        float a0 = 0.f, a1 = 0.f, a2 = 0.f, a3 = 0.f;
#pragma unroll 8
        for (int k = 0; k < 64; k += 4) {
            a0 += xk[k]     * W[k       * HID + col];
            a1 += xk[k + 1] * W[(k + 1) * HID + col];
            a2 += xk[k + 2] * W[(k + 2) * HID + col];
            a3 += xk[k + 3] * W[(k + 3) * HID + col];
        }
        part[q * 256 + col] = (a0 + a1) + (a2 + a3);
    }
    __syncthreads();
    if (q == 0) y1[col] = fmaxf((part[col] + part[256 + col]) + (part[512 + col] + part[768 + col]) + f1b[col], 0.f);
    __syncthreads();

    {
        const float* W = f2w + q * 64 * HID;
        const float* xk = y1 + q * 64;
        float a0 = 0.f, a1 = 0.f, a2 = 0.f, a3 = 0.f;
#pragma unroll 8
        for (int k = 0; k < 64; k += 4) {
            a0 += xk[k]     * W[k       * HID + col];
            a1 += xk[k + 1] * W[(k + 1) * HID + col];
            a2 += xk[k + 2] * W[(k + 2) * HID + col];
            a3 += xk[k + 3] * W[(k + 3) * HID + col];
        }
        part[q * 256 + col] = (a0 + a1) + (a2 + a3);
    }
    __syncthreads();
    if (q == 0) y2[col] = fmaxf((part[col] + part[256 + col]) + (part[512 + col] + part[768 + col]) + f2b[col], 0.f);
    __syncthreads();

    if (tid < 256) {
        int o = tid & 31, q8 = tid >> 5;
        if (o < 28) {
            const float* W = f3w + q8 * 32 * 28;
            const float* xk = y2 + q8 * 32;
            float a0 = 0.f, a1 = 0.f;
#pragma unroll
            for (int k = 0; k < 32; k += 2) {
                a0 += xk[k]     * W[k       * 28 + o];
                a1 += xk[k + 1] * W[(k + 1) * 28 + o];
            }
            part[q8 * 28 + o] = a0 + a1;
        }
    }
    __syncthreads();

    if (tid < 32) {
        float z;
        if (tid < 28) {
            z = f3b[tid];
#pragma unroll
            for (int p = 0; p < 8; p++) z += part[p * 28 + tid];
        } else {
            z = -1e30f;
        }
        float m = z;
#pragma unroll
        for (int o = 16; o > 0; o >>= 1) m = fmaxf(m, __shfl_xor_sync(0xffffffffu, m, o));
        float e = (tid < 28) ? expf(z - m) : 0.f;
        float se = e;
#pragma unroll
        for (int o = 16; o > 0; o >>= 1) se += __shfl_xor_sync(0xffffffffu, se, o);
        if (tid < 28) out[b * 28 + tid] = z - m - logf(se);
    }
}

// ---------------- launch ----------------
extern "C" void kernel_launch(void* const* d_in, const int* in_sizes, int n_in,
                              void* d_out, int out_size) {
    (void)in_sizes; (void)n_in; (void)out_size;
    const float* x   = (const float*)d_in[0];
    const float* qst = (const float*)d_in[1];
    const float* g1w = (const float*)d_in[2];
    const float* g1b = (const float*)d_in[3];
    const float* g2w = (const float*)d_in[4];
    const float* g2b = (const float*)d_in[5];
    const float* g3w = (const float*)d_in[6];
    const float* g3b = (const float*)d_in[7];
    const float* g4w = (const float*)d_in[8];
    const float* g4b = (const float*)d_in[9];
    const float* f1w = (const float*)d_in[10];
    const float* f1b = (const float*)d_in[11];
    const float* f2w = (const float*)d_in[12];
    const float* f2b = (const float*)d_in[13];
    const float* f3w = (const float*)d_in[14];
    const float* f3b = (const float*)d_in[15];
    float* out = (float*)d_out;

    cudaFuncSetAttribute((const void*)k2, cudaFuncAttributeMaxDynamicSharedMemorySize, (int)K2_SMEM);

    k0<<<524, 256>>>(x, qst, g1w, g1b, g2w, g3w, g4w);
    k2<<<NCTA2, 256, K2_SMEM>>>(g2b, g3b, g4b);
    k3<<<64, 1024>>>(f1w, f1b, f2w, f2b, f3w, f3b, out);
}

// round 16
// speedup vs baseline: 2.0836x; 1.0436x over previous
#include <cuda_runtime.h>
#include <cuda_fp16.h>
#include <cstdint>
#include <cstddef>

#define HID   256
#define NOBJ  64
#define BATCH 64
#define NCTA2 8192          // 64 b x 64 i x 2 j-halves

// ---------------- static device scratch ----------------
__device__ float g_U[BATCH * NOBJ * HID];    // xf @ W1[0:26]
__device__ float g_VQ[BATCH * NOBJ * HID];   // xf @ W1[26:52] + qst @ W1[52:180] + b1
__device__ uint4 g_Bh4[3 * 4 * 2048];        // 3 layers x 4 K-chunks x 32KB fragment-packed fp16 B
__device__ float g_partial[NCTA2 * HID];

// ---------------- helpers ----------------
__device__ __forceinline__ void mma16816(float acc[4], uint32_t a0, uint32_t a1, uint32_t a2, uint32_t a3,
                                         uint32_t b0, uint32_t b1) {
    asm volatile("mma.sync.aligned.m16n8k16.row.col.f32.f16.f16.f32 "
                 "{%0,%1,%2,%3}, {%4,%5,%6,%7}, {%8,%9}, {%0,%1,%2,%3};"
                 : "+f"(acc[0]), "+f"(acc[1]), "+f"(acc[2]), "+f"(acc[3])
                 : "r"(a0), "r"(a1), "r"(a2), "r"(a3), "r"(b0), "r"(b1));
}
__device__ __forceinline__ uint32_t pack2(__half lo, __half hi) {
    return (uint32_t)__half_as_ushort(lo) | ((uint32_t)__half_as_ushort(hi) << 16);
}

// ---------------- k0: weight-pack (blocks 0..11) + first-layer projections (blocks 12..523) ----------------
// Projection CTA = (b, h-half, j-quarter): 128 h-cols x 16 j-rows; thread = (h, jsub) with 8 j-rows.
__global__ __launch_bounds__(256) void k0(const float* __restrict__ x,
                                          const float* __restrict__ qst,
                                          const float* __restrict__ w1,
                                          const float* __restrict__ b1,
                                          const float* __restrict__ w2,
                                          const float* __restrict__ w3,
                                          const float* __restrict__ w4) {
    __shared__ __align__(16) unsigned char sraw[64 * 256 * 2];   // 32KB
    int bx = blockIdx.x, tid = threadIdx.x;

    if (bx < 12) {
        __half* sh = (__half*)sraw;
        int l = bx >> 2, kc = bx & 3;
        const float* src = (l == 0) ? w2 : (l == 1) ? w3 : w4;
#pragma unroll 8
        for (int p = 0; p < 64; p++) {
            int idx = tid + p * 256;
            sh[idx] = __float2half_rn(src[kc * 64 * 256 + idx]);
        }
        __syncthreads();
        uint4* dst = g_Bh4 + (l * 4 + kc) * 2048;
#pragma unroll
        for (int e0 = 0; e0 < 8; e0++) {
            int e = e0 * 256 + tid;
            int lane = e & 31, npair = (e >> 5) & 7, ks = (e >> 8) & 3, wn = e >> 10;
            int g = lane >> 2, t4 = lane & 3;
            int k0 = ks * 16 + 2 * t4;
            int n0 = wn * 128 + npair * 16 + g;
            uint4 v;
            v.x = pack2(sh[k0 * 256 + n0],       sh[(k0 + 1) * 256 + n0]);
            v.y = pack2(sh[(k0 + 8) * 256 + n0], sh[(k0 + 9) * 256 + n0]);
            v.z = pack2(sh[k0 * 256 + n0 + 8],       sh[(k0 + 1) * 256 + n0 + 8]);
            v.w = pack2(sh[(k0 + 8) * 256 + n0 + 8], sh[(k0 + 9) * 256 + n0 + 8]);
            dst[e] = v;
        }
    } else {
        float* xfs = (float*)sraw;            // [16][26]
        float* qs  = xfs + 16 * 26;           // [128]
        int bb = bx - 12;                     // 0..511
        int b  = bb >> 3;
        int hh = (bb >> 2) & 1;
        int jq = bb & 3;
        int j0 = jq * 16;
        int h  = (tid & 127) + hh * 128;
        int jsub = tid >> 7;                  // 0/1: which 8 of the 16 j rows

        for (int idx = tid; idx < 16 * 26; idx += 256) {
            int jl = idx / 26, c = idx % 26;
            int j = j0 + jl;
            float v;
            if (c < 24)       v = x[((size_t)b * 24 + c) * 64 + j];
            else if (c == 24) v = ((float)j * 0.125f - 4.0f) * 0.25f;
            else              v = ((float)(j & 7) - 4.0f) * 0.25f;
            xfs[jl * 26 + c] = v;
        }
        if (tid < 128) qs[tid] = qst[b * 128 + tid];
        __syncthreads();

        float wa[26], wb[26];
#pragma unroll
        for (int c = 0; c < 26; c++) {
            wa[c] = w1[c * HID + h];
            wb[c] = w1[(26 + c) * HID + h];
        }
        float q0 = b1[h], q1 = 0.f, q2 = 0.f, q3 = 0.f;
#pragma unroll 8
        for (int q = 0; q < 128; q += 4) {
            q0 += qs[q]     * w1[(52 + q)     * HID + h];
            q1 += qs[q + 1] * w1[(52 + q + 1) * HID + h];
            q2 += qs[q + 2] * w1[(52 + q + 2) * HID + h];
            q3 += qs[q + 3] * w1[(52 + q + 3) * HID + h];
        }
        float qp = (q0 + q1) + (q2 + q3);

#pragma unroll
        for (int t = 0; t < 8; t++) {
            int jl = jsub * 8 + t;
            float u = 0.f, v = 0.f;
#pragma unroll
            for (int c = 0; c < 26; c++) {
                u += xfs[jl * 26 + c] * wa[c];
                v += xfs[jl * 26 + c] * wb[c];
            }
            g_U[((size_t)b * NOBJ + j0 + jl) * HID + h]  = u;
            g_VQ[((size_t)b * NOBJ + j0 + jl) * HID + h] = v + qp;
        }
    }
}

// ---------------- k2: fused g2->g3->g4 + pair-sum, M=32 tiles, 4 CTAs/SM, B via LDG, A double-buffered ----------------
// CTA = (b, i, j-half): M=32 rows, N=256, K=256, 3 layers. 4 warps: wn=warp owns a unique 64-col slice.
// A smem: 2 x 16KB buffers ([kc(4)][ks(4)][mt(2)][lane(32)] x 16B). 3 barriers per CTA.
// Last layer: warp-local shfl reduction -> direct g_partial store (no wsum smem stage).
#define BIAS_OFF 32768u
#define K2_SMEM  35840u

__global__ __launch_bounds__(128, 4) void k2(const float* __restrict__ gb2,
                                             const float* __restrict__ gb3,
                                             const float* __restrict__ gb4) {
    extern __shared__ unsigned char sm[];
    float* biasS = (float*)(sm + BIAS_OFF);   // [3][256]

    const int tid = threadIdx.x, lane = tid & 31, warp = tid >> 5;
    const int wn = warp;                       // 0..3, 64 columns each
    const int g = lane >> 2, t4 = lane & 3;
    const int b = blockIdx.x >> 7;
    const int rem = blockIdx.x & 127;
    const int i0 = rem >> 1, j0 = (rem & 1) * 32;

    biasS[tid]       = gb2[tid]; biasS[tid + 128]       = gb2[tid + 128];
    biasS[256 + tid] = gb3[tid]; biasS[256 + tid + 128] = gb3[tid + 128];
    biasS[512 + tid] = gb4[tid]; biasS[512 + tid + 128] = gb4[tid + 128];

    // build layer-1 activations (32 rows) into buffer 0, fragment layout
    {
        unsigned char* A0 = sm;
        const float* Ub = g_U  + ((size_t)b * NOBJ + j0) * HID;
        const float* Vb = g_VQ + ((size_t)b * NOBJ + i0) * HID;
        int k0 = tid * 2;                      // each thread: one k-pair, all 32 rows
        int kc = k0 >> 6, ks = (k0 >> 4) & 3, t4s = (k0 & 7) >> 1, pairsel = (k0 >> 3) & 1;
        float2 v = *(const float2*)(Vb + k0);  // constant across rows for this CTA
#pragma unroll 8
        for (int row = 0; row < 32; row++) {
            float2 u = *(const float2*)(Ub + row * HID + k0);
            __half h0 = __float2half_rn(fmaxf(u.x + v.x, 0.f));
            __half h1 = __float2half_rn(fmaxf(u.y + v.y, 0.f));
            int mts = (row >> 4) & 1, g8 = (row >> 3) & 1, gs = row & 7;
            int lanes = gs * 4 + t4s;
            uint32_t off = (uint32_t)((((kc * 4 + ks) * 2 + mts) * 32 + lanes) * 16
                                      + pairsel * 8 + g8 * 4);
            *(uint32_t*)(A0 + off) = pack2(h0, h1);
        }
    }
    __syncthreads();   // A buffer 0 + biasS visible to all warps

    // per-warp constant part of the B fragment entry index within a (l,kc) block
    const int bent = (((wn >> 1) * 4) * 8 + (wn & 1) * 4) * 32 + lane;   // + ks*8*32 + np*32

#pragma unroll 1
    for (int l = 0; l < 3; l++) {
        unsigned char* Acur  = sm + (uint32_t)((l & 1) * 16384);
        unsigned char* Anext = sm + (uint32_t)(((l + 1) & 1) * 16384);

        // init accumulators with bias (epilogue then needs only relu)
        float acc[2][8][4];
#pragma unroll
        for (int nt = 0; nt < 8; nt++) {
            int c0 = wn * 64 + nt * 8 + 2 * t4;
            float bz0 = biasS[l * 256 + c0], bz1 = biasS[l * 256 + c0 + 1];
#pragma unroll
            for (int mt = 0; mt < 2; mt++) {
                acc[mt][nt][0] = bz0; acc[mt][nt][1] = bz1; acc[mt][nt][2] = bz0; acc[mt][nt][3] = bz1;
            }
        }

        const uint4* Bl = g_Bh4 + (size_t)l * 4 * 2048;
#pragma unroll
        for (int kc = 0; kc < 4; kc++) {
            const uint4* Bk = Bl + kc * 2048 + bent;
#pragma unroll
            for (int ks = 0; ks < 4; ks++) {
                uint4 bb[4];
#pragma unroll
                for (int np = 0; np < 4; np++)
                    bb[np] = __ldg(Bk + ks * 256 + np * 32);
#pragma unroll
                for (int mt = 0; mt < 2; mt++) {
                    uint4 a = *(const uint4*)(Acur +
                        (size_t)(((((kc * 4 + ks) * 2 + mt) * 32) + lane) * 16));
#pragma unroll
                    for (int nt = 0; nt < 8; nt++) {
                        int np = nt >> 1, s = (nt & 1) * 2;
                        uint32_t b0 = (s == 0) ? bb[np].x : bb[np].z;
                        uint32_t b1 = (s == 0) ? bb[np].y : bb[np].w;
                        mma16816(acc[mt][nt], a.x, a.y, a.z, a.w, b0, b1);
                    }
                }
            }
        }

        if (l < 2) {
            // epilogue writes the OTHER buffer -> no barrier needed before it
#pragma unroll
            for (int mt = 0; mt < 2; mt++)
#pragma unroll
                for (int nt = 0; nt < 8; nt++) {
                    int c0 = wn * 64 + nt * 8 + 2 * t4;
                    __half2 hg  = __halves2half2(__float2half_rn(fmaxf(acc[mt][nt][0], 0.f)),
                                                 __float2half_rn(fmaxf(acc[mt][nt][1], 0.f)));
                    __half2 hg8 = __halves2half2(__float2half_rn(fmaxf(acc[mt][nt][2], 0.f)),
                                                 __float2half_rn(fmaxf(acc[mt][nt][3], 0.f)));
                    int kcn = c0 >> 6, ksn = (c0 >> 4) & 3, pairsel = (c0 >> 3) & 1;
                    uint32_t off = (uint32_t)((((kcn * 4 + ksn) * 2 + mt) * 32 + lane) * 16 + pairsel * 8);
                    uint2 st; st.x = *(uint32_t*)&hg; st.y = *(uint32_t*)&hg8;
                    *(uint2*)(Anext + off) = st;
                }
            __syncthreads();   // epilogue writes visible before next layer's A reads
        } else {
            // final layer: relu + warp-local column reduction, direct global store
#pragma unroll
            for (int nt = 0; nt < 8; nt++) {
                int c0 = wn * 64 + nt * 8 + 2 * t4;
                float s0 = fmaxf(acc[0][nt][0], 0.f) + fmaxf(acc[0][nt][2], 0.f)
                         + fmaxf(acc[1][nt][0], 0.f) + fmaxf(acc[1][nt][2], 0.f);
                float s1 = fmaxf(acc[0][nt][1], 0.f) + fmaxf(acc[0][nt][3], 0.f)
                         + fmaxf(acc[1][nt][1], 0.f) + fmaxf(acc[1][nt][3], 0.f);
                s0 += __shfl_xor_sync(0xffffffffu, s0, 4);
                s0 += __shfl_xor_sync(0xffffffffu, s0, 8);
                s0 += __shfl_xor_sync(0xffffffffu, s0, 16);
                s1 += __shfl_xor_sync(0xffffffffu, s1, 4);
                s1 += __shfl_xor_sync(0xffffffffu, s1, 8);
                s1 += __shfl_xor_sync(0xffffffffu, s1, 16);
                if (g == 0) {   // lanes 0..3 hold distinct columns; warps own disjoint 64-col slices
                    g_partial[(size_t)blockIdx.x * HID + c0]     = s0;
                    g_partial[(size_t)blockIdx.x * HID + c0 + 1] = s1;
                }
            }
        }
    }
}

// ---------------- k3: tile reduction (128 tiles) + f-MLP + log_softmax (1024 threads, k-split) ----------------
__global__ __launch_bounds__(1024) void k3(const float* __restrict__ f1w, const float* __restrict__ f1b,
                                           const float* __restrict__ f2w, const float* __restrict__ f2b,
                                           const float* __restrict__ f3w, const float* __restrict__ f3b,
                                           float* __restrict__ out) {
    __shared__ float part[4 * 256];
    __shared__ float xg[HID], y1[HID], y2[HID];
    int b = blockIdx.x, tid = threadIdx.x;
    int col = tid & 255, q = tid >> 8;

    {
        float s = 0.f;
#pragma unroll
        for (int t = 0; t < 32; t++)
            s += g_partial[((size_t)b * 128 + q * 32 + t) * HID + col];
        part[q * 256 + col] = s;
    }
    __syncthreads();
    if (q == 0) xg[col] = (part[col] + part[256 + col]) + (part[512 + col] + part[768 + col]);
    __syncthreads();

    {
        const float* W = f1w + q * 64 * HID;
        const float* xk = xg + q * 64;
        float a0 = 0.f, a1 = 0.f, a2 = 0.f, a3 = 0.f;
#pragma unroll 8
        for (int k = 0; k < 64; k += 4) {
            a0 += xk[k]     * W[k       * HID + col];
            a1 += xk[k + 1] * W[(k + 1) * HID + col];
            a2 += xk[k + 2] * W[(k + 2) * HID + col];
            a3 += xk[k + 3] * W[(k + 3) * HID + col];
        }
        part[q * 256 + col] = (a0 + a1) + (a2 + a3);
    }
    __syncthreads();
    if (q == 0) y1[col] = fmaxf((part[col] + part[256 + col]) + (part[512 + col] + part[768 + col]) + f1b[col], 0.f);
    __syncthreads();

    {
        const float* W = f2w + q * 64 * HID;
        const float* xk = y1 + q * 64;
        float a0 = 0.f, a1 = 0.f, a2 = 0.f, a3 = 0.f;
#pragma unroll 8
        for (int k = 0; k < 64; k += 4) {
            a0 += xk[k]     * W[k       * HID + col];
            a1 += xk[k + 1] * W[(k + 1) * HID + col];
            a2 += xk[k + 2] * W[(k + 2) * HID + col];
            a3 += xk[k + 3] * W[(k + 3) * HID + col];
        }
        part[q * 256 + col] = (a0 + a1) + (a2 + a3);
    }
    __syncthreads();
    if (q == 0) y2[col] = fmaxf((part[col] + part[256 + col]) + (part[512 + col] + part[768 + col]) + f2b[col], 0.f);
    __syncthreads();

    if (tid < 256) {
        int o = tid & 31, q8 = tid >> 5;
        if (o < 28) {
            const float* W = f3w + q8 * 32 * 28;
            const float* xk = y2 + q8 * 32;
            float a0 = 0.f, a1 = 0.f;
#pragma unroll
            for (int k = 0; k < 32; k += 2) {
                a0 += xk[k]     * W[k       * 28 + o];
                a1 += xk[k + 1] * W[(k + 1) * 28 + o];
            }
            part[q8 * 28 + o] = a0 + a1;
        }
    }
    __syncthreads();

    if (tid < 32) {
        float z;
        if (tid < 28) {
            z = f3b[tid];
#pragma unroll
            for (int p = 0; p < 8; p++) z += part[p * 28 + tid];
        } else {
            z = -1e30f;
        }
        float m = z;
#pragma unroll
        for (int o = 16; o > 0; o >>= 1) m = fmaxf(m, __shfl_xor_sync(0xffffffffu, m, o));
        float e = (tid < 28) ? expf(z - m) : 0.f;
        float se = e;
#pragma unroll
        for (int o = 16; o > 0; o >>= 1) se += __shfl_xor_sync(0xffffffffu, se, o);
        if (tid < 28) out[b * 28 + tid] = z - m - logf(se);
    }
}

// ---------------- launch ----------------
extern "C" void kernel_launch(void* const* d_in, const int* in_sizes, int n_in,
                              void* d_out, int out_size) {
    (void)in_sizes; (void)n_in; (void)out_size;
    const float* x   = (const float*)d_in[0];
    const float* qst = (const float*)d_in[1];
    const float* g1w = (const float*)d_in[2];
    const float* g1b = (const float*)d_in[3];
    const float* g2w = (const float*)d_in[4];
    const float* g2b = (const float*)d_in[5];
    const float* g3w = (const float*)d_in[6];
    const float* g3b = (const float*)d_in[7];
    const float* g4w = (const float*)d_in[8];
    const float* g4b = (const float*)d_in[9];
    const float* f1w = (const float*)d_in[10];
    const float* f1b = (const float*)d_in[11];
    const float* f2w = (const float*)d_in[12];
    const float* f2b = (const float*)d_in[13];
    const float* f3w = (const float*)d_in[14];
    const float* f3b = (const float*)d_in[15];
    float* out = (float*)d_out;

    cudaFuncSetAttribute((const void*)k2, cudaFuncAttributeMaxDynamicSharedMemorySize, (int)K2_SMEM);

    k0<<<524, 256>>>(x, qst, g1w, g1b, g2w, g3w, g4w);
    k2<<<NCTA2, 128, K2_SMEM>>>(g2b, g3b, g4b);
    k3<<<64, 1024>>>(f1w, f1b, f2w, f2b, f3w, f3b, out);
}